// round 11
// baseline (speedup 1.0000x reference)
#include <cuda_runtime.h>
#include <math.h>

#define NPTS   2048
#define IDIM   16
#define HDIM   32
#define JSPLIT 9
#define JCHUNK 228          // 8*228 + 224 = 2048
#define TILE_I 128
#define PTS_PER_WARP 8

typedef unsigned long long ull;

// ---------------- device scratch ----------------
__device__ float4 g_pts4[NPTS];
__device__ float4 g_nrm4[NPTS];
__device__ float  g_z   [NPTS * HDIM];
__device__ float  g_partial[JSPLIT][NPTS * HDIM];
__device__ float  g_stats[8];   // mu[0..3], rstd[4..7]

__device__ __forceinline__ float leakyf(float x) { return x >= 0.f ? x : 0.2f * x; }

// ---------------- packed f32x2 (native 64-bit regs, sm_103a) ----------------
__device__ __forceinline__ ull fma2(ull a, ull b, ull c) {
    ull d; asm("fma.rn.f32x2 %0, %1, %2, %3;" : "=l"(d) : "l"(a), "l"(b), "l"(c)); return d;
}
__device__ __forceinline__ ull mul2(ull a, ull b) {
    ull d; asm("mul.rn.f32x2 %0, %1, %2;" : "=l"(d) : "l"(a), "l"(b)); return d;
}
__device__ __forceinline__ ull pack2(float lo, float hi) {
    ull d; asm("mov.b64 %0, {%1, %2};" : "=l"(d) : "f"(lo), "f"(hi)); return d;
}
__device__ __forceinline__ float2 unpack2(ull a) {
    float2 v; asm("mov.b64 {%0, %1}, %2;" : "=f"(v.x), "=f"(v.y) : "l"(a)); return v;
}

// ---------------- net_in: 8 points per warp + prep ----------------
__global__ void k_netin(const float* __restrict__ points, const float* __restrict__ nuv,
                        const float* __restrict__ x,
                        const float* __restrict__ W1, const float* __restrict__ b1,
                        const float* __restrict__ W2, const float* __restrict__ b2) {
    __shared__ float sW1t[IDIM * HDIM];   // [c][h]
    __shared__ float sW2t[HDIM * HDIM];   // [c][h]
    __shared__ float sb1[HDIM], sb2[HDIM];
    int tid = threadIdx.x;
    for (int k = tid; k < HDIM * IDIM; k += 256) {
        int h = k / IDIM, c = k % IDIM;
        sW1t[c * HDIM + h] = W1[k];
    }
    for (int k = tid; k < HDIM * HDIM; k += 256) {
        int h = k >> 5, c = k & 31;
        sW2t[c * HDIM + h] = W2[k];
    }
    if (tid < HDIM) { sb1[tid] = b1[tid]; sb2[tid] = b2[tid]; }
    __syncthreads();

    int wid  = tid >> 5;
    int lane = tid & 31;
    int n0   = (blockIdx.x * 8 + wid) * PTS_PER_WARP;

    // prefetch inputs for all 8 points (MLP=8)
    float xi[PTS_PER_WARP];
#pragma unroll
    for (int p = 0; p < PTS_PER_WARP; p++)
        xi[p] = (lane < IDIM) ? x[(n0 + p) * IDIM + lane] : 0.f;

    // prep: 8 points handled by first 8 lanes (one each)
    if (lane < PTS_PER_WARP) {
        int n = n0 + lane;
        const float s = 0.07856742013183862f;  // 1/(sqrt(2)*9)
        g_pts4[n] = make_float4(points[n*3] * s, points[n*3+1] * s, points[n*3+2] * s, 0.f);
        g_nrm4[n] = make_float4(nuv[n*9], nuv[n*9+1], nuv[n*9+2], 0.f);
    }

#pragma unroll
    for (int p = 0; p < PTS_PER_WARP; p++) {
        float acc = sb1[lane];
#pragma unroll
        for (int c = 0; c < IDIM; c++)
            acc = fmaf(sW1t[c * HDIM + lane], __shfl_sync(0xffffffffu, xi[p], c), acc);
        float z1 = leakyf(acc);

        acc = sb2[lane];
#pragma unroll
        for (int c = 0; c < HDIM; c++)
            acc = fmaf(sW2t[c * HDIM + lane], __shfl_sync(0xffffffffu, z1, c), acc);
        g_z[(n0 + p) * HDIM + lane] = leakyf(acc);
    }
}

// ---------------- group-norm stats (fp32 inner, fp64 final) ----------------
__global__ void k_gstats(const float* __restrict__ z) {
    __shared__ float sh_s[1024], sh_q[1024];
    __shared__ double sd_s[32], sd_q[32];
    int tid = threadIdx.x;
    int c = tid & 31;
    int r0 = tid >> 5;
    float s = 0.f, q = 0.f;
    for (int it = 0; it < NPTS / 32; it++) {
        float v = z[(r0 + 32 * it) * HDIM + c];
        s += v;
        q = fmaf(v, v, q);
    }
    sh_s[tid] = s; sh_q[tid] = q;
    __syncthreads();
    if (tid < 32) {
        double S = 0.0, Q = 0.0;
        for (int m = 0; m < 32; m++) { S += (double)sh_s[tid + 32 * m]; Q += (double)sh_q[tid + 32 * m]; }
        sd_s[tid] = S; sd_q[tid] = Q;
    }
    __syncthreads();
    if (tid < 4) {
        double S = 0.0, Q = 0.0;
        for (int cc = tid * 8; cc < tid * 8 + 8; cc++) { S += sd_s[cc]; Q += sd_q[cc]; }
        double cntd = (double)NPTS * 8.0;
        double mu = S / cntd;
        double var = Q / cntd - mu * mu;
        g_stats[tid]     = (float)mu;
        g_stats[4 + tid] = (float)(1.0 / sqrt(var + 1e-5));
    }
}

// ---------------- apply group norm (final output, float4) ----------------
__global__ void k_gnorm(const float* __restrict__ z, const float* __restrict__ gamma,
                        const float* __restrict__ beta, float* __restrict__ out) {
    int idx = blockIdx.x * blockDim.x + threadIdx.x;   // one float4
    if (idx >= NPTS * HDIM / 4) return;
    int q = idx & 7;           // float4 within the 32-channel row
    int c0 = q * 4;
    float4 v = ((const float4*)z)[idx];
    int g0 = c0 >> 3, g1 = (c0 + 2) >> 3;
    float4 o;
    o.x = (v.x - g_stats[g0]) * g_stats[4 + g0] * gamma[c0]     + beta[c0];
    o.y = (v.y - g_stats[g0]) * g_stats[4 + g0] * gamma[c0 + 1] + beta[c0 + 1];
    o.z = (v.z - g_stats[g1]) * g_stats[4 + g1] * gamma[c0 + 2] + beta[c0 + 2];
    o.w = (v.w - g_stats[g1]) * g_stats[4 + g1] * gamma[c0 + 3] + beta[c0 + 3];
    ((float4*)out)[idx] = o;
}

// ---------------- pairwise interaction: folded frame (M=A1@u), dual packed dots ----------------
__global__ void __launch_bounds__(TILE_I, 2)
k_pair(const float* __restrict__ nuv,
       const float* __restrict__ A1, const float* __restrict__ B1,
       const float* __restrict__ A2, const float* __restrict__ B2,
       const float* __restrict__ gamma, const float* __restrict__ beta) {
    __shared__ ulonglong2 sDa[JCHUNK];   // {(pjx,njx),(pjy,njy)}
    __shared__ ulonglong2 sDb[JCHUNK];   // {(pjz,njz),(|pj|^2, 0)}
    __shared__ ulonglong2 sBa[JCHUNK];   // {(pjx,pjx),(pjy,pjy)}
    __shared__ ull        sBz[JCHUNK];   // (pjz,pjz)
    __shared__ __align__(16) float sF[JCHUNK][HDIM];
    __shared__ float smu[4], srs[4];

    int tid = threadIdx.x;
    int j0  = blockIdx.y * JCHUNK;
    int cnt = min(JCHUNK, NPTS - j0);

    if (tid < 4) { smu[tid] = g_stats[tid]; srs[tid] = g_stats[4 + tid]; }
    __syncthreads();   // smu/srs before sF fill

    for (int k = tid; k < cnt; k += TILE_I) {
        float4 pj = g_pts4[j0 + k];
        float4 nj = g_nrm4[j0 + k];
        float w2j = fmaf(pj.x, pj.x, fmaf(pj.y, pj.y, pj.z * pj.z));
        ulonglong2 da; da.x = pack2(pj.x, nj.x); da.y = pack2(pj.y, nj.y);
        ulonglong2 db; db.x = pack2(pj.z, nj.z); db.y = pack2(w2j, 0.f);
        ulonglong2 ba; ba.x = pack2(pj.x, pj.x); ba.y = pack2(pj.y, pj.y);
        sDa[k] = da; sDb[k] = db; sBa[k] = ba; sBz[k] = pack2(pj.z, pj.z);
    }
    for (int k = tid; k < cnt * (HDIM / 4); k += TILE_I) {
        int r = k >> 3, q = k & 7;
        float4 v = ((const float4*)g_z)[(j0 + r) * (HDIM / 4) + q];
        int c0 = q * 4;
        int g0 = c0 >> 3;
        float4 o;
        o.x = (v.x - smu[g0]) * srs[g0] * gamma[c0]     + beta[c0];
        o.y = (v.y - smu[g0]) * srs[g0] * gamma[c0 + 1] + beta[c0 + 1];
        int g1 = (c0 + 2) >> 3;
        o.z = (v.z - smu[g1]) * srs[g1] * gamma[c0 + 2] + beta[c0 + 2];
        o.w = (v.w - smu[g1]) * srs[g1] * gamma[c0 + 3] + beta[c0 + 3];
        ((float4*)sF)[k] = o;
    }
    __syncthreads();

    int half  = tid >> 6;
    int iloc  = tid & 63;
    int i     = blockIdx.x * 64 + iloc;
    int hbase = half * 16;

    float4 p4 = g_pts4[i];
    float4 n4 = g_nrm4[i];
    float ci = fmaf(p4.x, p4.x, fmaf(p4.y, p4.y, p4.z * p4.z));   // |p_i|^2
    ull pin0 = pack2(p4.x, n4.x), pin1 = pack2(p4.y, n4.y), pin2 = pack2(p4.z, n4.z);

    // M = A1 @ u_i (8x3), b1i = B1 - M . p_i  -> cut = M . p_j + b1i
    float M[24], b1i[8];
    {
        float u[9];
#pragma unroll
        for (int k = 0; k < 9; k++) u[k] = nuv[i * 9 + k];
#pragma unroll
        for (int k = 0; k < 8; k++) {
            float a0 = A1[k * 3], a1 = A1[k * 3 + 1], a2 = A1[k * 3 + 2];
#pragma unroll
            for (int c = 0; c < 3; c++)
                M[k * 3 + c] = fmaf(a0, u[c], fmaf(a1, u[3 + c], a2 * u[6 + c]));
            b1i[k] = B1[k] - (fmaf(M[k*3], p4.x, fmaf(M[k*3+1], p4.y, M[k*3+2] * p4.z)));
        }
    }
    ull m[12], b1ip[4];
#pragma unroll
    for (int comp = 0; comp < 3; comp++)
#pragma unroll
        for (int q = 0; q < 4; q++)
            m[comp * 4 + q] = pack2(M[(2*q) * 3 + comp], M[(2*q+1) * 3 + comp]);
#pragma unroll
    for (int q = 0; q < 4; q++) b1ip[q] = pack2(b1i[2*q], b1i[2*q+1]);

    // register-resident packed A2 slab: a2p[hp][c] = (A2[2hp][c], A2[2hp+1][c])
    ull a2p[64];
    ull b2p[8];
#pragma unroll
    for (int hp = 0; hp < 8; hp++) {
        int h0 = hbase + 2 * hp;
        float4 r0a = ((const float4*)A2)[h0 * 2];
        float4 r0b = ((const float4*)A2)[h0 * 2 + 1];
        float4 r1a = ((const float4*)A2)[(h0 + 1) * 2];
        float4 r1b = ((const float4*)A2)[(h0 + 1) * 2 + 1];
        a2p[hp * 8 + 0] = pack2(r0a.x, r1a.x);
        a2p[hp * 8 + 1] = pack2(r0a.y, r1a.y);
        a2p[hp * 8 + 2] = pack2(r0a.z, r1a.z);
        a2p[hp * 8 + 3] = pack2(r0a.w, r1a.w);
        a2p[hp * 8 + 4] = pack2(r0b.x, r1b.x);
        a2p[hp * 8 + 5] = pack2(r0b.y, r1b.y);
        a2p[hp * 8 + 6] = pack2(r0b.z, r1b.z);
        a2p[hp * 8 + 7] = pack2(r0b.w, r1b.w);
        b2p[hp] = pack2(B2[h0], B2[h0 + 1]);
    }

    ull acc[8];
#pragma unroll
    for (int hp = 0; hp < 8; hp++) acc[hp] = 0ull;

#pragma unroll 2
    for (int j = 0; j < cnt; j++) {
        ulonglong2 da = sDa[j];
        ulonglong2 db = sDb[j];
        // dual dot: (p_i . p_j, n_i . n_j) in one packed chain
        ull dual = fma2(pin0, da.x, fma2(pin1, da.y, mul2(pin2, db.x)));
        float2 dd = unpack2(dual);
        float w2j = unpack2(db.y).x;
        float sq  = fmaf(-2.f, dd.x, ci + w2j);
        float t   = 2.f - dd.y;
        float w   = __expf(-(sq * t) * t);
        ull  w2   = pack2(w, w);

        // cut layer: M.p_j + b1i, packed across (c,c+1); relu via FMNMX (ALU)
        ulonglong2 ba = sBa[j];
        ull bz = sBz[j];
        ull xcb[8];
#pragma unroll
        for (int q = 0; q < 4; q++) {
            ull s = fma2(m[q], ba.x, fma2(m[4 + q], ba.y, fma2(m[8 + q], bz, b1ip[q])));
            float2 v = unpack2(s);
            v.x = fmaxf(v.x, 0.f);
            v.y = fmaxf(v.y, 0.f);
            xcb[2*q]     = pack2(v.x, v.x);
            xcb[2*q + 1] = pack2(v.y, v.y);
        }

        const ulonglong2* frow = (const ulonglong2*)&sF[j][hbase];
#pragma unroll
        for (int q2 = 0; q2 < 4; q2++) {
            ulonglong2 fq = frow[q2];
#pragma unroll
            for (int hh = 0; hh < 2; hh++) {
                int hp = 2 * q2 + hh;
                ull wf = mul2(w2, hh ? fq.y : fq.x);
                const ull* ar = a2p + hp * 8;
                ull s = b2p[hp];
#pragma unroll
                for (int c = 0; c < 8; c++) s = fma2(ar[c], xcb[c], s);
                float2 v = unpack2(s);          // relu via 2x FMNMX (ALU pipe)
                v.x = fmaxf(v.x, 0.f);
                v.y = fmaxf(v.y, 0.f);
                acc[hp] = fma2(pack2(v.x, v.y), wf, acc[hp]);
            }
        }
    }

    ulonglong2* outp = (ulonglong2*)&g_partial[blockIdx.y][i * HDIM + hbase];
#pragma unroll
    for (int q = 0; q < 4; q++) {
        ulonglong2 v; v.x = acc[2*q]; v.y = acc[2*q+1];
        outp[q] = v;
    }
}

// ---------------- reduce(9) + net_out: 8 points per warp ----------------
__global__ void k_netout(const float* __restrict__ W1, const float* __restrict__ b1,
                         const float* __restrict__ W2, const float* __restrict__ b2) {
    __shared__ float sW1t[HDIM * HDIM], sW2t[HDIM * HDIM], sb1[HDIM], sb2[HDIM];
    int tid = threadIdx.x;
    for (int k = tid; k < HDIM * HDIM; k += 256) {
        int h = k >> 5, c = k & 31;
        sW1t[c * HDIM + h] = W1[k];
        sW2t[c * HDIM + h] = W2[k];
    }
    if (tid < HDIM) { sb1[tid] = b1[tid]; sb2[tid] = b2[tid]; }
    __syncthreads();

    int wid  = tid >> 5;
    int lane = tid & 31;
    int n0   = (blockIdx.x * 8 + wid) * PTS_PER_WARP;

    // prefetch + reduce partials for all 8 points (MLP = 8*9)
    float xi[PTS_PER_WARP];
#pragma unroll
    for (int p = 0; p < PTS_PER_WARP; p++) {
        float s = 0.f;
#pragma unroll
        for (int q = 0; q < JSPLIT; q++) s += g_partial[q][(n0 + p) * HDIM + lane];
        xi[p] = s;
    }

#pragma unroll
    for (int p = 0; p < PTS_PER_WARP; p++) {
        float acc = sb1[lane];
#pragma unroll
        for (int c = 0; c < HDIM; c++)
            acc = fmaf(sW1t[c * HDIM + lane], __shfl_sync(0xffffffffu, xi[p], c), acc);
        float z1 = leakyf(acc);

        acc = sb2[lane];
#pragma unroll
        for (int c = 0; c < HDIM; c++)
            acc = fmaf(sW2t[c * HDIM + lane], __shfl_sync(0xffffffffu, z1, c), acc);
        g_z[(n0 + p) * HDIM + lane] = leakyf(acc);
    }
}

// ---------------- launch ----------------
extern "C" void kernel_launch(void* const* d_in, const int* in_sizes, int n_in,
                              void* d_out, int out_size) {
    const float* points  = (const float*)d_in[0];
    const float* nuv     = (const float*)d_in[1];
    const float* feats   = (const float*)d_in[2];
    const float* W_in1   = (const float*)d_in[3];
    const float* b_in1   = (const float*)d_in[4];
    const float* W_in2   = (const float*)d_in[5];
    const float* b_in2   = (const float*)d_in[6];
    const float* g_in_w  = (const float*)d_in[7];
    const float* g_in_b  = (const float*)d_in[8];
    const float* A1      = (const float*)d_in[9];
    const float* A2      = (const float*)d_in[10];
    const float* W_out1  = (const float*)d_in[11];
    const float* b_out1  = (const float*)d_in[12];
    const float* W_out2  = (const float*)d_in[13];
    const float* b_out2  = (const float*)d_in[14];
    const float* g_out_w = (const float*)d_in[15];
    const float* g_out_b = (const float*)d_in[16];
    const float* B1      = (const float*)d_in[17];
    const float* B2      = (const float*)d_in[18];

    float* p_z;
    cudaGetSymbolAddress((void**)&p_z, g_z);

    k_netin<<<NPTS / 64, 256>>>(points, nuv, feats, W_in1, b_in1, W_in2, b_in2);
    k_gstats<<<1, 1024>>>(p_z);
    k_pair<<<dim3(NPTS / 64, JSPLIT), TILE_I>>>(nuv, A1, B1, A2, B2, g_in_w, g_in_b);
    k_netout<<<NPTS / 64, 256>>>(W_out1, b_out1, W_out2, b_out2);
    k_gstats<<<1, 1024>>>(p_z);
    k_gnorm<<<(NPTS * HDIM / 4) / 256, 256>>>(p_z, g_out_w, g_out_b, (float*)d_out);
}

// round 12
// speedup vs baseline: 1.8113x; 1.8113x over previous
#include <cuda_runtime.h>
#include <math.h>

#define NPTS   2048
#define IDIM   16
#define HDIM   32
#define JSPLIT 9
#define JCHUNK 228          // 8*228 + 224 = 2048
#define TILE_I 128

typedef unsigned long long ull;

// ---------------- device scratch ----------------
__device__ float4 g_pts4[NPTS];
__device__ float4 g_nrm4[NPTS];
__device__ float  g_z   [NPTS * HDIM];
__device__ float  g_partial[JSPLIT][NPTS * HDIM];
__device__ float  g_stats[8];   // mu[0..3], rstd[4..7]

__device__ __forceinline__ float leakyf(float x) { return x >= 0.f ? x : 0.2f * x; }

// ---------------- packed f32x2 (native 64-bit regs, sm_103a) ----------------
__device__ __forceinline__ ull fma2(ull a, ull b, ull c) {
    ull d; asm("fma.rn.f32x2 %0, %1, %2, %3;" : "=l"(d) : "l"(a), "l"(b), "l"(c)); return d;
}
__device__ __forceinline__ ull mul2(ull a, ull b) {
    ull d; asm("mul.rn.f32x2 %0, %1, %2;" : "=l"(d) : "l"(a), "l"(b)); return d;
}
__device__ __forceinline__ ull pack2(float lo, float hi) {
    ull d; asm("mov.b64 %0, {%1, %2};" : "=l"(d) : "f"(lo), "f"(hi)); return d;
}
__device__ __forceinline__ float2 unpack2(ull a) {
    float2 v; asm("mov.b64 {%0, %1}, %2;" : "=f"(v.x), "=f"(v.y) : "l"(a)); return v;
}

// ---------------- net_in: warp per point + prep (512-thread blocks) ----------------
__global__ void k_netin(const float* __restrict__ points, const float* __restrict__ nuv,
                        const float* __restrict__ x,
                        const float* __restrict__ W1, const float* __restrict__ b1,
                        const float* __restrict__ W2, const float* __restrict__ b2) {
    __shared__ float sW1t[IDIM * HDIM];   // [c][h]
    __shared__ float sW2t[HDIM * HDIM];   // [c][h]
    __shared__ float sb1[HDIM], sb2[HDIM];
    int tid = threadIdx.x;
    for (int k = tid; k < HDIM * IDIM; k += 512) {
        int h = k / IDIM, c = k % IDIM;
        sW1t[c * HDIM + h] = W1[k];
    }
    for (int k = tid; k < HDIM * HDIM; k += 512) {
        int h = k >> 5, c = k & 31;
        sW2t[c * HDIM + h] = W2[k];
    }
    if (tid < HDIM) { sb1[tid] = b1[tid]; sb2[tid] = b2[tid]; }
    __syncthreads();

    int n    = blockIdx.x * 16 + (tid >> 5);
    int lane = tid & 31;

    if (lane == 0) {
        const float s = 0.07856742013183862f;  // 1/(sqrt(2)*9)
        g_pts4[n] = make_float4(points[n*3] * s, points[n*3+1] * s, points[n*3+2] * s, 0.f);
        g_nrm4[n] = make_float4(nuv[n*9], nuv[n*9+1], nuv[n*9+2], 0.f);
    }

    float xi = (lane < IDIM) ? x[n * IDIM + lane] : 0.f;

    float acc = sb1[lane];
#pragma unroll
    for (int c = 0; c < IDIM; c++)
        acc = fmaf(sW1t[c * HDIM + lane], __shfl_sync(0xffffffffu, xi, c), acc);
    float z1 = leakyf(acc);

    acc = sb2[lane];
#pragma unroll
    for (int c = 0; c < HDIM; c++)
        acc = fmaf(sW2t[c * HDIM + lane], __shfl_sync(0xffffffffu, z1, c), acc);
    g_z[n * HDIM + lane] = leakyf(acc);
}

// ---------------- group-norm stats: float4 loads, pairwise fp32, fp64 finish ----------------
__global__ void k_gstats(const float* __restrict__ z) {
    __shared__ float sh_s[1024], sh_q[1024];
    int tid = threadIdx.x;
    int q  = tid & 7;        // which float4 of the 8 per row (fixed -> fixed group q>>1)
    int r0 = tid >> 3;       // starting row (0..127)
    float s = 0.f, qs = 0.f;
#pragma unroll
    for (int it = 0; it < NPTS / 128; it++) {           // 16 float4 loads
        float4 v = ((const float4*)z)[(r0 + 128 * it) * (HDIM / 4) + q];
        s  += (v.x + v.y) + (v.z + v.w);
        qs += fmaf(v.x, v.x, v.y * v.y) + fmaf(v.z, v.z, v.w * v.w);
    }
    sh_s[tid] = s; sh_q[tid] = qs;
    __syncthreads();
    // tree over the row dimension (index difference multiple of 8 keeps q fixed)
    for (int off = 512; off >= 8; off >>= 1) {
        if (tid < off) { sh_s[tid] += sh_s[tid + off]; sh_q[tid] += sh_q[tid + off]; }
        __syncthreads();
    }
    if (tid < 4) {   // group g sums = q=2g and q=2g+1
        double S = (double)sh_s[2*tid] + (double)sh_s[2*tid+1];
        double Q = (double)sh_q[2*tid] + (double)sh_q[2*tid+1];
        double cntd = (double)NPTS * 8.0;
        double mu = S / cntd;
        double var = Q / cntd - mu * mu;
        g_stats[tid]     = (float)mu;
        g_stats[4 + tid] = (float)(1.0 / sqrt(var + 1e-5));
    }
}

// ---------------- apply group norm (final output, float4) ----------------
__global__ void k_gnorm(const float* __restrict__ z, const float* __restrict__ gamma,
                        const float* __restrict__ beta, float* __restrict__ out) {
    int idx = blockIdx.x * blockDim.x + threadIdx.x;   // one float4
    if (idx >= NPTS * HDIM / 4) return;
    int q = idx & 7;
    int c0 = q * 4;
    float4 v = ((const float4*)z)[idx];
    int g0 = c0 >> 3, g1 = (c0 + 2) >> 3;
    float4 o;
    o.x = (v.x - g_stats[g0]) * g_stats[4 + g0] * gamma[c0]     + beta[c0];
    o.y = (v.y - g_stats[g0]) * g_stats[4 + g0] * gamma[c0 + 1] + beta[c0 + 1];
    o.z = (v.z - g_stats[g1]) * g_stats[4 + g1] * gamma[c0 + 2] + beta[c0 + 2];
    o.w = (v.w - g_stats[g1]) * g_stats[4 + g1] * gamma[c0 + 3] + beta[c0 + 3];
    ((float4*)out)[idx] = o;
}

// ---------------- pairwise interaction: folded frame (M=A1@u), dual packed dots ----------------
__global__ void __launch_bounds__(TILE_I, 2)
k_pair(const float* __restrict__ nuv,
       const float* __restrict__ A1, const float* __restrict__ B1,
       const float* __restrict__ A2, const float* __restrict__ B2,
       const float* __restrict__ gamma, const float* __restrict__ beta) {
    __shared__ ulonglong2 sDa[JCHUNK];   // {(pjx,njx),(pjy,njy)}
    __shared__ ulonglong2 sDb[JCHUNK];   // {(pjz,njz),(|pj|^2, 0)}
    __shared__ ulonglong2 sBa[JCHUNK];   // {(pjx,pjx),(pjy,pjy)}
    __shared__ ull        sBz[JCHUNK];   // (pjz,pjz)
    __shared__ __align__(16) float sF[JCHUNK][HDIM];
    __shared__ float smu[4], srs[4];

    int tid = threadIdx.x;
    int j0  = blockIdx.y * JCHUNK;
    int cnt = min(JCHUNK, NPTS - j0);

    if (tid < 4) { smu[tid] = g_stats[tid]; srs[tid] = g_stats[4 + tid]; }
    __syncthreads();   // smu/srs before sF fill

    for (int k = tid; k < cnt; k += TILE_I) {
        float4 pj = g_pts4[j0 + k];
        float4 nj = g_nrm4[j0 + k];
        float w2j = fmaf(pj.x, pj.x, fmaf(pj.y, pj.y, pj.z * pj.z));
        ulonglong2 da; da.x = pack2(pj.x, nj.x); da.y = pack2(pj.y, nj.y);
        ulonglong2 db; db.x = pack2(pj.z, nj.z); db.y = pack2(w2j, 0.f);
        ulonglong2 ba; ba.x = pack2(pj.x, pj.x); ba.y = pack2(pj.y, pj.y);
        sDa[k] = da; sDb[k] = db; sBa[k] = ba; sBz[k] = pack2(pj.z, pj.z);
    }
    for (int k = tid; k < cnt * (HDIM / 4); k += TILE_I) {
        int r = k >> 3, q = k & 7;
        float4 v = ((const float4*)g_z)[(j0 + r) * (HDIM / 4) + q];
        int c0 = q * 4;
        int g0 = c0 >> 3;
        float4 o;
        o.x = (v.x - smu[g0]) * srs[g0] * gamma[c0]     + beta[c0];
        o.y = (v.y - smu[g0]) * srs[g0] * gamma[c0 + 1] + beta[c0 + 1];
        int g1 = (c0 + 2) >> 3;
        o.z = (v.z - smu[g1]) * srs[g1] * gamma[c0 + 2] + beta[c0 + 2];
        o.w = (v.w - smu[g1]) * srs[g1] * gamma[c0 + 3] + beta[c0 + 3];
        ((float4*)sF)[k] = o;
    }
    __syncthreads();

    int half  = tid >> 6;
    int iloc  = tid & 63;
    int i     = blockIdx.x * 64 + iloc;
    int hbase = half * 16;

    float4 p4 = g_pts4[i];
    float4 n4 = g_nrm4[i];
    float ci = fmaf(p4.x, p4.x, fmaf(p4.y, p4.y, p4.z * p4.z));   // |p_i|^2
    ull pin0 = pack2(p4.x, n4.x), pin1 = pack2(p4.y, n4.y), pin2 = pack2(p4.z, n4.z);

    // M = A1 @ u_i (8x3), b1i = B1 - M . p_i  -> cut = M . p_j + b1i
    float M[24], b1i[8];
    {
        float u[9];
#pragma unroll
        for (int k = 0; k < 9; k++) u[k] = nuv[i * 9 + k];
#pragma unroll
        for (int k = 0; k < 8; k++) {
            float a0 = A1[k * 3], a1 = A1[k * 3 + 1], a2 = A1[k * 3 + 2];
#pragma unroll
            for (int c = 0; c < 3; c++)
                M[k * 3 + c] = fmaf(a0, u[c], fmaf(a1, u[3 + c], a2 * u[6 + c]));
            b1i[k] = B1[k] - (fmaf(M[k*3], p4.x, fmaf(M[k*3+1], p4.y, M[k*3+2] * p4.z)));
        }
    }
    ull m[12], b1ip[4];
#pragma unroll
    for (int comp = 0; comp < 3; comp++)
#pragma unroll
        for (int q = 0; q < 4; q++)
            m[comp * 4 + q] = pack2(M[(2*q) * 3 + comp], M[(2*q+1) * 3 + comp]);
#pragma unroll
    for (int q = 0; q < 4; q++) b1ip[q] = pack2(b1i[2*q], b1i[2*q+1]);

    // register-resident packed A2 slab: a2p[hp][c] = (A2[2hp][c], A2[2hp+1][c])
    ull a2p[64];
    ull b2p[8];
#pragma unroll
    for (int hp = 0; hp < 8; hp++) {
        int h0 = hbase + 2 * hp;
        float4 r0a = ((const float4*)A2)[h0 * 2];
        float4 r0b = ((const float4*)A2)[h0 * 2 + 1];
        float4 r1a = ((const float4*)A2)[(h0 + 1) * 2];
        float4 r1b = ((const float4*)A2)[(h0 + 1) * 2 + 1];
        a2p[hp * 8 + 0] = pack2(r0a.x, r1a.x);
        a2p[hp * 8 + 1] = pack2(r0a.y, r1a.y);
        a2p[hp * 8 + 2] = pack2(r0a.z, r1a.z);
        a2p[hp * 8 + 3] = pack2(r0a.w, r1a.w);
        a2p[hp * 8 + 4] = pack2(r0b.x, r1b.x);
        a2p[hp * 8 + 5] = pack2(r0b.y, r1b.y);
        a2p[hp * 8 + 6] = pack2(r0b.z, r1b.z);
        a2p[hp * 8 + 7] = pack2(r0b.w, r1b.w);
        b2p[hp] = pack2(B2[h0], B2[h0 + 1]);
    }

    ull acc[8];
#pragma unroll
    for (int hp = 0; hp < 8; hp++) acc[hp] = 0ull;

#pragma unroll 2
    for (int j = 0; j < cnt; j++) {
        ulonglong2 da = sDa[j];
        ulonglong2 db = sDb[j];
        // dual dot: (p_i . p_j, n_i . n_j) in one packed chain
        ull dual = fma2(pin0, da.x, fma2(pin1, da.y, mul2(pin2, db.x)));
        float2 dd = unpack2(dual);
        float w2j = unpack2(db.y).x;
        float sq  = fmaf(-2.f, dd.x, ci + w2j);
        float t   = 2.f - dd.y;
        float w   = __expf(-(sq * t) * t);
        ull  w2   = pack2(w, w);

        // cut layer: M.p_j + b1i, packed across (c,c+1); relu via FMNMX (ALU)
        ulonglong2 ba = sBa[j];
        ull bz = sBz[j];
        ull xcb[8];
#pragma unroll
        for (int q = 0; q < 4; q++) {
            ull s = fma2(m[q], ba.x, fma2(m[4 + q], ba.y, fma2(m[8 + q], bz, b1ip[q])));
            float2 v = unpack2(s);
            v.x = fmaxf(v.x, 0.f);
            v.y = fmaxf(v.y, 0.f);
            xcb[2*q]     = pack2(v.x, v.x);
            xcb[2*q + 1] = pack2(v.y, v.y);
        }

        const ulonglong2* frow = (const ulonglong2*)&sF[j][hbase];
#pragma unroll
        for (int q2 = 0; q2 < 4; q2++) {
            ulonglong2 fq = frow[q2];
#pragma unroll
            for (int hh = 0; hh < 2; hh++) {
                int hp = 2 * q2 + hh;
                ull wf = mul2(w2, hh ? fq.y : fq.x);
                const ull* ar = a2p + hp * 8;
                ull s = b2p[hp];
#pragma unroll
                for (int c = 0; c < 8; c++) s = fma2(ar[c], xcb[c], s);
                float2 v = unpack2(s);          // relu via 2x FMNMX (ALU pipe)
                v.x = fmaxf(v.x, 0.f);
                v.y = fmaxf(v.y, 0.f);
                acc[hp] = fma2(pack2(v.x, v.y), wf, acc[hp]);
            }
        }
    }

    ulonglong2* outp = (ulonglong2*)&g_partial[blockIdx.y][i * HDIM + hbase];
#pragma unroll
    for (int q = 0; q < 4; q++) {
        ulonglong2 v; v.x = acc[2*q]; v.y = acc[2*q+1];
        outp[q] = v;
    }
}

// ---------------- reduce(9) + net_out: warp per point (512-thread blocks) ----------------
__global__ void k_netout(const float* __restrict__ W1, const float* __restrict__ b1,
                         const float* __restrict__ W2, const float* __restrict__ b2) {
    __shared__ float sW1t[HDIM * HDIM], sW2t[HDIM * HDIM], sb1[HDIM], sb2[HDIM];
    int tid = threadIdx.x;
    for (int k = tid; k < HDIM * HDIM; k += 512) {
        int h = k >> 5, c = k & 31;
        sW1t[c * HDIM + h] = W1[k];
        sW2t[c * HDIM + h] = W2[k];
    }
    if (tid < HDIM) { sb1[tid] = b1[tid]; sb2[tid] = b2[tid]; }
    __syncthreads();

    int n    = blockIdx.x * 16 + (tid >> 5);
    int lane = tid & 31;

    // 9 independent loads (MLP=9) -> latency mostly overlapped
    float xi = 0.f;
#pragma unroll
    for (int p = 0; p < JSPLIT; p++) xi += g_partial[p][n * HDIM + lane];

    float acc = sb1[lane];
#pragma unroll
    for (int c = 0; c < HDIM; c++)
        acc = fmaf(sW1t[c * HDIM + lane], __shfl_sync(0xffffffffu, xi, c), acc);
    float z1 = leakyf(acc);

    acc = sb2[lane];
#pragma unroll
    for (int c = 0; c < HDIM; c++)
        acc = fmaf(sW2t[c * HDIM + lane], __shfl_sync(0xffffffffu, z1, c), acc);
    g_z[n * HDIM + lane] = leakyf(acc);
}

// ---------------- launch ----------------
extern "C" void kernel_launch(void* const* d_in, const int* in_sizes, int n_in,
                              void* d_out, int out_size) {
    const float* points  = (const float*)d_in[0];
    const float* nuv     = (const float*)d_in[1];
    const float* feats   = (const float*)d_in[2];
    const float* W_in1   = (const float*)d_in[3];
    const float* b_in1   = (const float*)d_in[4];
    const float* W_in2   = (const float*)d_in[5];
    const float* b_in2   = (const float*)d_in[6];
    const float* g_in_w  = (const float*)d_in[7];
    const float* g_in_b  = (const float*)d_in[8];
    const float* A1      = (const float*)d_in[9];
    const float* A2      = (const float*)d_in[10];
    const float* W_out1  = (const float*)d_in[11];
    const float* b_out1  = (const float*)d_in[12];
    const float* W_out2  = (const float*)d_in[13];
    const float* b_out2  = (const float*)d_in[14];
    const float* g_out_w = (const float*)d_in[15];
    const float* g_out_b = (const float*)d_in[16];
    const float* B1      = (const float*)d_in[17];
    const float* B2      = (const float*)d_in[18];

    float* p_z;
    cudaGetSymbolAddress((void**)&p_z, g_z);

    k_netin<<<NPTS / 16, 512>>>(points, nuv, feats, W_in1, b_in1, W_in2, b_in2);
    k_gstats<<<1, 1024>>>(p_z);
    k_pair<<<dim3(NPTS / 64, JSPLIT), TILE_I>>>(nuv, A1, B1, A2, B2, g_in_w, g_in_b);
    k_netout<<<NPTS / 16, 512>>>(W_out1, b_out1, W_out2, b_out2);
    k_gstats<<<1, 1024>>>(p_z);
    k_gnorm<<<(NPTS * HDIM / 4) / 256, 256>>>(p_z, g_out_w, g_out_b, (float*)d_out);
}

// round 13
// speedup vs baseline: 1.8170x; 1.0032x over previous
#include <cuda_runtime.h>
#include <math.h>

#define NPTS   2048
#define IDIM   16
#define HDIM   32
#define JSPLIT 9
#define JCHUNK 228          // 8*228 + 224 = 2048
#define TILE_I 128

typedef unsigned long long ull;

// ---------------- device scratch ----------------
__device__ float4 g_pts4[NPTS];
__device__ float4 g_nrm4[NPTS];
__device__ float  g_z   [NPTS * HDIM];
__device__ float  g_partial[JSPLIT][NPTS * HDIM];
__device__ float  g_stats[8];   // mu[0..3], rstd[4..7]

__device__ __forceinline__ float leakyf(float x) { return x >= 0.f ? x : 0.2f * x; }

// ---------------- packed f32x2 (native 64-bit regs, sm_103a) ----------------
__device__ __forceinline__ ull fma2(ull a, ull b, ull c) {
    ull d; asm("fma.rn.f32x2 %0, %1, %2, %3;" : "=l"(d) : "l"(a), "l"(b), "l"(c)); return d;
}
__device__ __forceinline__ ull mul2(ull a, ull b) {
    ull d; asm("mul.rn.f32x2 %0, %1, %2;" : "=l"(d) : "l"(a), "l"(b)); return d;
}
__device__ __forceinline__ ull pack2(float lo, float hi) {
    ull d; asm("mov.b64 %0, {%1, %2};" : "=l"(d) : "f"(lo), "f"(hi)); return d;
}
__device__ __forceinline__ float2 unpack2(ull a) {
    float2 v; asm("mov.b64 {%0, %1}, %2;" : "=f"(v.x), "=f"(v.y) : "l"(a)); return v;
}

// ---------------- net_in: warp per point, SMEM-broadcast dot products ----------------
__global__ void k_netin(const float* __restrict__ points, const float* __restrict__ nuv,
                        const float* __restrict__ x,
                        const float* __restrict__ W1, const float* __restrict__ b1,
                        const float* __restrict__ W2, const float* __restrict__ b2) {
    __shared__ float sW1t[IDIM * HDIM];   // [c][h]
    __shared__ float sW2t[HDIM * HDIM];   // [c][h]
    __shared__ float sb1[HDIM], sb2[HDIM];
    __shared__ float sX[16][HDIM];        // per-warp activation buffer
    int tid = threadIdx.x;
    for (int k = tid; k < HDIM * IDIM; k += 512) {
        int h = k / IDIM, c = k % IDIM;
        sW1t[c * HDIM + h] = W1[k];
    }
    for (int k = tid; k < HDIM * HDIM; k += 512) {
        int h = k >> 5, c = k & 31;
        sW2t[c * HDIM + h] = W2[k];
    }
    if (tid < HDIM) { sb1[tid] = b1[tid]; sb2[tid] = b2[tid]; }
    __syncthreads();

    int wid  = tid >> 5;
    int n    = blockIdx.x * 16 + wid;
    int lane = tid & 31;

    if (lane == 0) {
        const float s = 0.07856742013183862f;  // 1/(sqrt(2)*9)
        g_pts4[n] = make_float4(points[n*3] * s, points[n*3+1] * s, points[n*3+2] * s, 0.f);
        g_nrm4[n] = make_float4(nuv[n*9], nuv[n*9+1], nuv[n*9+2], 0.f);
    }

    sX[wid][lane] = (lane < IDIM) ? x[n * IDIM + lane] : 0.f;
    __syncwarp();

    // layer 1: 16 independent broadcast-LDS, 4 partial accumulators
    float a0 = 0.f, a1 = 0.f, a2 = 0.f, a3 = 0.f;
#pragma unroll
    for (int c = 0; c < IDIM; c += 4) {
        a0 = fmaf(sW1t[(c    ) * HDIM + lane], sX[wid][c    ], a0);
        a1 = fmaf(sW1t[(c + 1) * HDIM + lane], sX[wid][c + 1], a1);
        a2 = fmaf(sW1t[(c + 2) * HDIM + lane], sX[wid][c + 2], a2);
        a3 = fmaf(sW1t[(c + 3) * HDIM + lane], sX[wid][c + 3], a3);
    }
    float z1 = leakyf(((a0 + a1) + (a2 + a3)) + sb1[lane]);

    __syncwarp();
    sX[wid][lane] = z1;
    __syncwarp();

    // layer 2
    a0 = a1 = a2 = a3 = 0.f;
#pragma unroll
    for (int c = 0; c < HDIM; c += 4) {
        a0 = fmaf(sW2t[(c    ) * HDIM + lane], sX[wid][c    ], a0);
        a1 = fmaf(sW2t[(c + 1) * HDIM + lane], sX[wid][c + 1], a1);
        a2 = fmaf(sW2t[(c + 2) * HDIM + lane], sX[wid][c + 2], a2);
        a3 = fmaf(sW2t[(c + 3) * HDIM + lane], sX[wid][c + 3], a3);
    }
    g_z[n * HDIM + lane] = leakyf(((a0 + a1) + (a2 + a3)) + sb2[lane]);
}

// ---------------- group-norm stats: float4 loads, pairwise fp32, fp64 finish ----------------
__global__ void k_gstats(const float* __restrict__ z) {
    __shared__ float sh_s[1024], sh_q[1024];
    int tid = threadIdx.x;
    int q  = tid & 7;        // which float4 of the 8 per row (fixed -> fixed group q>>1)
    int r0 = tid >> 3;       // starting row (0..127)
    float s = 0.f, qs = 0.f;
#pragma unroll
    for (int it = 0; it < NPTS / 128; it++) {           // 16 float4 loads
        float4 v = ((const float4*)z)[(r0 + 128 * it) * (HDIM / 4) + q];
        s  += (v.x + v.y) + (v.z + v.w);
        qs += fmaf(v.x, v.x, v.y * v.y) + fmaf(v.z, v.z, v.w * v.w);
    }
    sh_s[tid] = s; sh_q[tid] = qs;
    __syncthreads();
    for (int off = 512; off >= 8; off >>= 1) {
        if (tid < off) { sh_s[tid] += sh_s[tid + off]; sh_q[tid] += sh_q[tid + off]; }
        __syncthreads();
    }
    if (tid < 4) {
        double S = (double)sh_s[2*tid] + (double)sh_s[2*tid+1];
        double Q = (double)sh_q[2*tid] + (double)sh_q[2*tid+1];
        double cntd = (double)NPTS * 8.0;
        double mu = S / cntd;
        double var = Q / cntd - mu * mu;
        g_stats[tid]     = (float)mu;
        g_stats[4 + tid] = (float)(1.0 / sqrt(var + 1e-5));
    }
}

// ---------------- apply group norm (final output, float4) ----------------
__global__ void k_gnorm(const float* __restrict__ z, const float* __restrict__ gamma,
                        const float* __restrict__ beta, float* __restrict__ out) {
    int idx = blockIdx.x * blockDim.x + threadIdx.x;   // one float4
    if (idx >= NPTS * HDIM / 4) return;
    int q = idx & 7;
    int c0 = q * 4;
    float4 v = ((const float4*)z)[idx];
    int g0 = c0 >> 3, g1 = (c0 + 2) >> 3;
    float4 o;
    o.x = (v.x - g_stats[g0]) * g_stats[4 + g0] * gamma[c0]     + beta[c0];
    o.y = (v.y - g_stats[g0]) * g_stats[4 + g0] * gamma[c0 + 1] + beta[c0 + 1];
    o.z = (v.z - g_stats[g1]) * g_stats[4 + g1] * gamma[c0 + 2] + beta[c0 + 2];
    o.w = (v.w - g_stats[g1]) * g_stats[4 + g1] * gamma[c0 + 3] + beta[c0 + 3];
    ((float4*)out)[idx] = o;
}

// ---------------- pairwise interaction: folded frame (M=A1@u), dual packed dots ----------------
__global__ void __launch_bounds__(TILE_I, 2)
k_pair(const float* __restrict__ nuv,
       const float* __restrict__ A1, const float* __restrict__ B1,
       const float* __restrict__ A2, const float* __restrict__ B2,
       const float* __restrict__ gamma, const float* __restrict__ beta) {
    __shared__ ulonglong2 sDa[JCHUNK];   // {(pjx,njx),(pjy,njy)}
    __shared__ ulonglong2 sDb[JCHUNK];   // {(pjz,njz),(|pj|^2, 0)}
    __shared__ ulonglong2 sBa[JCHUNK];   // {(pjx,pjx),(pjy,pjy)}
    __shared__ ull        sBz[JCHUNK];   // (pjz,pjz)
    __shared__ __align__(16) float sF[JCHUNK][HDIM];
    __shared__ float smu[4], srs[4];

    int tid = threadIdx.x;
    int j0  = blockIdx.y * JCHUNK;
    int cnt = min(JCHUNK, NPTS - j0);

    if (tid < 4) { smu[tid] = g_stats[tid]; srs[tid] = g_stats[4 + tid]; }
    __syncthreads();   // smu/srs before sF fill

    for (int k = tid; k < cnt; k += TILE_I) {
        float4 pj = g_pts4[j0 + k];
        float4 nj = g_nrm4[j0 + k];
        float w2j = fmaf(pj.x, pj.x, fmaf(pj.y, pj.y, pj.z * pj.z));
        ulonglong2 da; da.x = pack2(pj.x, nj.x); da.y = pack2(pj.y, nj.y);
        ulonglong2 db; db.x = pack2(pj.z, nj.z); db.y = pack2(w2j, 0.f);
        ulonglong2 ba; ba.x = pack2(pj.x, pj.x); ba.y = pack2(pj.y, pj.y);
        sDa[k] = da; sDb[k] = db; sBa[k] = ba; sBz[k] = pack2(pj.z, pj.z);
    }
    for (int k = tid; k < cnt * (HDIM / 4); k += TILE_I) {
        int r = k >> 3, q = k & 7;
        float4 v = ((const float4*)g_z)[(j0 + r) * (HDIM / 4) + q];
        int c0 = q * 4;
        int g0 = c0 >> 3;
        float4 o;
        o.x = (v.x - smu[g0]) * srs[g0] * gamma[c0]     + beta[c0];
        o.y = (v.y - smu[g0]) * srs[g0] * gamma[c0 + 1] + beta[c0 + 1];
        int g1 = (c0 + 2) >> 3;
        o.z = (v.z - smu[g1]) * srs[g1] * gamma[c0 + 2] + beta[c0 + 2];
        o.w = (v.w - smu[g1]) * srs[g1] * gamma[c0 + 3] + beta[c0 + 3];
        ((float4*)sF)[k] = o;
    }
    __syncthreads();

    int half  = tid >> 6;
    int iloc  = tid & 63;
    int i     = blockIdx.x * 64 + iloc;
    int hbase = half * 16;

    float4 p4 = g_pts4[i];
    float4 n4 = g_nrm4[i];
    float ci = fmaf(p4.x, p4.x, fmaf(p4.y, p4.y, p4.z * p4.z));   // |p_i|^2
    ull pin0 = pack2(p4.x, n4.x), pin1 = pack2(p4.y, n4.y), pin2 = pack2(p4.z, n4.z);

    // M = A1 @ u_i (8x3), b1i = B1 - M . p_i  -> cut = M . p_j + b1i
    float M[24], b1i[8];
    {
        float u[9];
#pragma unroll
        for (int k = 0; k < 9; k++) u[k] = nuv[i * 9 + k];
#pragma unroll
        for (int k = 0; k < 8; k++) {
            float a0 = A1[k * 3], a1 = A1[k * 3 + 1], a2 = A1[k * 3 + 2];
#pragma unroll
            for (int c = 0; c < 3; c++)
                M[k * 3 + c] = fmaf(a0, u[c], fmaf(a1, u[3 + c], a2 * u[6 + c]));
            b1i[k] = B1[k] - (fmaf(M[k*3], p4.x, fmaf(M[k*3+1], p4.y, M[k*3+2] * p4.z)));
        }
    }
    ull m[12], b1ip[4];
#pragma unroll
    for (int comp = 0; comp < 3; comp++)
#pragma unroll
        for (int q = 0; q < 4; q++)
            m[comp * 4 + q] = pack2(M[(2*q) * 3 + comp], M[(2*q+1) * 3 + comp]);
#pragma unroll
    for (int q = 0; q < 4; q++) b1ip[q] = pack2(b1i[2*q], b1i[2*q+1]);

    // register-resident packed A2 slab: a2p[hp][c] = (A2[2hp][c], A2[2hp+1][c])
    ull a2p[64];
    ull b2p[8];
#pragma unroll
    for (int hp = 0; hp < 8; hp++) {
        int h0 = hbase + 2 * hp;
        float4 r0a = ((const float4*)A2)[h0 * 2];
        float4 r0b = ((const float4*)A2)[h0 * 2 + 1];
        float4 r1a = ((const float4*)A2)[(h0 + 1) * 2];
        float4 r1b = ((const float4*)A2)[(h0 + 1) * 2 + 1];
        a2p[hp * 8 + 0] = pack2(r0a.x, r1a.x);
        a2p[hp * 8 + 1] = pack2(r0a.y, r1a.y);
        a2p[hp * 8 + 2] = pack2(r0a.z, r1a.z);
        a2p[hp * 8 + 3] = pack2(r0a.w, r1a.w);
        a2p[hp * 8 + 4] = pack2(r0b.x, r1b.x);
        a2p[hp * 8 + 5] = pack2(r0b.y, r1b.y);
        a2p[hp * 8 + 6] = pack2(r0b.z, r1b.z);
        a2p[hp * 8 + 7] = pack2(r0b.w, r1b.w);
        b2p[hp] = pack2(B2[h0], B2[h0 + 1]);
    }

    ull acc[8];
#pragma unroll
    for (int hp = 0; hp < 8; hp++) acc[hp] = 0ull;

#pragma unroll 2
    for (int j = 0; j < cnt; j++) {
        ulonglong2 da = sDa[j];
        ulonglong2 db = sDb[j];
        // dual dot: (p_i . p_j, n_i . n_j) in one packed chain
        ull dual = fma2(pin0, da.x, fma2(pin1, da.y, mul2(pin2, db.x)));
        float2 dd = unpack2(dual);
        float w2j = unpack2(db.y).x;
        float sq  = fmaf(-2.f, dd.x, ci + w2j);
        float t   = 2.f - dd.y;
        float w   = __expf(-(sq * t) * t);
        ull  w2   = pack2(w, w);

        // cut layer: M.p_j + b1i, packed across (c,c+1); relu via FMNMX (ALU)
        ulonglong2 ba = sBa[j];
        ull bz = sBz[j];
        ull xcb[8];
#pragma unroll
        for (int q = 0; q < 4; q++) {
            ull s = fma2(m[q], ba.x, fma2(m[4 + q], ba.y, fma2(m[8 + q], bz, b1ip[q])));
            float2 v = unpack2(s);
            v.x = fmaxf(v.x, 0.f);
            v.y = fmaxf(v.y, 0.f);
            xcb[2*q]     = pack2(v.x, v.x);
            xcb[2*q + 1] = pack2(v.y, v.y);
        }

        const ulonglong2* frow = (const ulonglong2*)&sF[j][hbase];
#pragma unroll
        for (int q2 = 0; q2 < 4; q2++) {
            ulonglong2 fq = frow[q2];
#pragma unroll
            for (int hh = 0; hh < 2; hh++) {
                int hp = 2 * q2 + hh;
                ull wf = mul2(w2, hh ? fq.y : fq.x);
                const ull* ar = a2p + hp * 8;
                ull s = b2p[hp];
#pragma unroll
                for (int c = 0; c < 8; c++) s = fma2(ar[c], xcb[c], s);
                float2 v = unpack2(s);          // relu via 2x FMNMX (ALU pipe)
                v.x = fmaxf(v.x, 0.f);
                v.y = fmaxf(v.y, 0.f);
                acc[hp] = fma2(pack2(v.x, v.y), wf, acc[hp]);
            }
        }
    }

    ulonglong2* outp = (ulonglong2*)&g_partial[blockIdx.y][i * HDIM + hbase];
#pragma unroll
    for (int q = 0; q < 4; q++) {
        ulonglong2 v; v.x = acc[2*q]; v.y = acc[2*q+1];
        outp[q] = v;
    }
}

// ---------------- reduce(9) + net_out: warp per point, SMEM-broadcast dots ----------------
__global__ void k_netout(const float* __restrict__ W1, const float* __restrict__ b1,
                         const float* __restrict__ W2, const float* __restrict__ b2) {
    __shared__ float sW1t[HDIM * HDIM], sW2t[HDIM * HDIM], sb1[HDIM], sb2[HDIM];
    __shared__ float sX[16][HDIM];
    int tid = threadIdx.x;
    for (int k = tid; k < HDIM * HDIM; k += 512) {
        int h = k >> 5, c = k & 31;
        sW1t[c * HDIM + h] = W1[k];
        sW2t[c * HDIM + h] = W2[k];
    }
    if (tid < HDIM) { sb1[tid] = b1[tid]; sb2[tid] = b2[tid]; }
    __syncthreads();

    int wid  = tid >> 5;
    int n    = blockIdx.x * 16 + wid;
    int lane = tid & 31;

    // 9 independent loads (MLP=9) -> latency mostly overlapped
    float xi = 0.f;
#pragma unroll
    for (int p = 0; p < JSPLIT; p++) xi += g_partial[p][n * HDIM + lane];

    sX[wid][lane] = xi;
    __syncwarp();

    float a0 = 0.f, a1 = 0.f, a2 = 0.f, a3 = 0.f;
#pragma unroll
    for (int c = 0; c < HDIM; c += 4) {
        a0 = fmaf(sW1t[(c    ) * HDIM + lane], sX[wid][c    ], a0);
        a1 = fmaf(sW1t[(c + 1) * HDIM + lane], sX[wid][c + 1], a1);
        a2 = fmaf(sW1t[(c + 2) * HDIM + lane], sX[wid][c + 2], a2);
        a3 = fmaf(sW1t[(c + 3) * HDIM + lane], sX[wid][c + 3], a3);
    }
    float z1 = leakyf(((a0 + a1) + (a2 + a3)) + sb1[lane]);

    __syncwarp();
    sX[wid][lane] = z1;
    __syncwarp();

    a0 = a1 = a2 = a3 = 0.f;
#pragma unroll
    for (int c = 0; c < HDIM; c += 4) {
        a0 = fmaf(sW2t[(c    ) * HDIM + lane], sX[wid][c    ], a0);
        a1 = fmaf(sW2t[(c + 1) * HDIM + lane], sX[wid][c + 1], a1);
        a2 = fmaf(sW2t[(c + 2) * HDIM + lane], sX[wid][c + 2], a2);
        a3 = fmaf(sW2t[(c + 3) * HDIM + lane], sX[wid][c + 3], a3);
    }
    g_z[n * HDIM + lane] = leakyf(((a0 + a1) + (a2 + a3)) + sb2[lane]);
}

// ---------------- launch ----------------
extern "C" void kernel_launch(void* const* d_in, const int* in_sizes, int n_in,
                              void* d_out, int out_size) {
    const float* points  = (const float*)d_in[0];
    const float* nuv     = (const float*)d_in[1];
    const float* feats   = (const float*)d_in[2];
    const float* W_in1   = (const float*)d_in[3];
    const float* b_in1   = (const float*)d_in[4];
    const float* W_in2   = (const float*)d_in[5];
    const float* b_in2   = (const float*)d_in[6];
    const float* g_in_w  = (const float*)d_in[7];
    const float* g_in_b  = (const float*)d_in[8];
    const float* A1      = (const float*)d_in[9];
    const float* A2      = (const float*)d_in[10];
    const float* W_out1  = (const float*)d_in[11];
    const float* b_out1  = (const float*)d_in[12];
    const float* W_out2  = (const float*)d_in[13];
    const float* b_out2  = (const float*)d_in[14];
    const float* g_out_w = (const float*)d_in[15];
    const float* g_out_b = (const float*)d_in[16];
    const float* B1      = (const float*)d_in[17];
    const float* B2      = (const float*)d_in[18];

    float* p_z;
    cudaGetSymbolAddress((void**)&p_z, g_z);

    k_netin<<<NPTS / 16, 512>>>(points, nuv, feats, W_in1, b_in1, W_in2, b_in2);
    k_gstats<<<1, 1024>>>(p_z);
    k_pair<<<dim3(NPTS / 64, JSPLIT), TILE_I>>>(nuv, A1, B1, A2, B2, g_in_w, g_in_b);
    k_netout<<<NPTS / 16, 512>>>(W_out1, b_out1, W_out2, b_out2);
    k_gstats<<<1, 1024>>>(p_z);
    k_gnorm<<<(NPTS * HDIM / 4) / 256, 256>>>(p_z, g_out_w, g_out_b, (float*)d_out);
}

// round 15
// speedup vs baseline: 1.8968x; 1.0439x over previous
#include <cuda_runtime.h>
#include <math.h>

#define NPTS   2048
#define IDIM   16
#define HDIM   32
#define JSPLIT 9
#define JCHUNK 228          // 8*228 + 224 = 2048
#define TILE_I 128
#define NETBLKS (NPTS / 16) // 128

typedef unsigned long long ull;

// ---------------- device scratch ----------------
__device__ float4 g_pts4[NPTS];
__device__ float4 g_nrm4[NPTS];
__device__ float  g_z   [NPTS * HDIM];
__device__ float  g_partial[JSPLIT][NPTS * HDIM];
__device__ float  g_stats[8];            // mu[0..3], rstd[4..7]
__device__ float  g_bs[NETBLKS][4];      // per-block group sums
__device__ float  g_bq[NETBLKS][4];      // per-block group sumsq
__device__ unsigned g_cnt = 0;           // last-block counter (self-resetting)

__device__ __forceinline__ float leakyf(float x) { return x >= 0.f ? x : 0.2f * x; }

// ---------------- packed f32x2 (native 64-bit regs, sm_103a) ----------------
__device__ __forceinline__ ull fma2(ull a, ull b, ull c) {
    ull d; asm("fma.rn.f32x2 %0, %1, %2, %3;" : "=l"(d) : "l"(a), "l"(b), "l"(c)); return d;
}
__device__ __forceinline__ ull mul2(ull a, ull b) {
    ull d; asm("mul.rn.f32x2 %0, %1, %2;" : "=l"(d) : "l"(a), "l"(b)); return d;
}
__device__ __forceinline__ ull pack2(float lo, float hi) {
    ull d; asm("mov.b64 %0, {%1, %2};" : "=l"(d) : "f"(lo), "f"(hi)); return d;
}
__device__ __forceinline__ float2 unpack2(ull a) {
    float2 v; asm("mov.b64 {%0, %1}, %2;" : "=f"(v.x), "=f"(v.y) : "l"(a)); return v;
}

// ---------------- fused block-level group stats + last-block finalize ----------------
// val: this thread's output value (channel = lane, group = lane>>3). grid must be NETBLKS.
__device__ __forceinline__ void stats_tail(float val, int lane, int wid, int tid,
                                           float (*sG)[4], float (*sGq)[4],
                                           float* sFin, float* sFinQ, int* sLast) {
    float s = val, q = val * val;
#pragma unroll
    for (int off = 4; off; off >>= 1) {
        s += __shfl_down_sync(0xffffffffu, s, off, 8);
        q += __shfl_down_sync(0xffffffffu, q, off, 8);
    }
    if ((lane & 7) == 0) { sG[wid][lane >> 3] = s; sGq[wid][lane >> 3] = q; }
    __syncthreads();
    if (tid == 0) {
#pragma unroll
        for (int g = 0; g < 4; g++) {
            float S = 0.f, Q = 0.f;
            for (int w = 0; w < 16; w++) { S += sG[w][g]; Q += sGq[w][g]; }
            g_bs[blockIdx.x][g] = S; g_bq[blockIdx.x][g] = Q;
        }
        __threadfence();
        unsigned old = atomicAdd(&g_cnt, 1u);
        *sLast = (old == NETBLKS - 1) ? 1 : 0;
    }
    __syncthreads();
    if (*sLast) {
        int b = tid & 127, g = tid >> 7;   // 512 threads cover 128 blocks x 4 groups
        sFin[g * 128 + b]  = g_bs[b][g];
        sFinQ[g * 128 + b] = g_bq[b][g];
        __syncthreads();
        for (int off = 64; off >= 1; off >>= 1) {
            if (b < off) {
                sFin[g * 128 + b]  += sFin[g * 128 + b + off];
                sFinQ[g * 128 + b] += sFinQ[g * 128 + b + off];
            }
            __syncthreads();
        }
        if (tid < 4) {
            double S = (double)sFin[tid * 128];
            double Q = (double)sFinQ[tid * 128];
            double cntd = (double)NPTS * 8.0;
            double mu = S / cntd;
            double var = Q / cntd - mu * mu;
            g_stats[tid]     = (float)mu;
            g_stats[4 + tid] = (float)(1.0 / sqrt(var + 1e-5));
        }
        if (tid == 0) g_cnt = 0;           // reset for next use / replay
    }
}

// ---------------- net_in + prep + fused group stats ----------------
__global__ void __launch_bounds__(512)
k_netin(const float* __restrict__ points, const float* __restrict__ nuv,
        const float* __restrict__ x,
        const float* __restrict__ W1, const float* __restrict__ b1,
        const float* __restrict__ W2, const float* __restrict__ b2) {
    __shared__ float sW1t[IDIM * HDIM];   // [c][h]
    __shared__ float sW2t[HDIM * HDIM];   // [c][h]
    __shared__ float sb1[HDIM], sb2[HDIM];
    __shared__ float sX[16][HDIM];
    __shared__ float sG[16][4], sGq[16][4];
    __shared__ float sFin[512], sFinQ[512];
    __shared__ int   sLast;

    int tid  = threadIdx.x;
    int wid  = tid >> 5;
    int lane = tid & 31;
    int n    = blockIdx.x * 16 + wid;

    // issue input loads FIRST (hide latency under weight staging)
    float xin = (lane < IDIM) ? x[n * IDIM + lane] : 0.f;

    if (lane == 0) {
        const float s = 0.07856742013183862f;  // 1/(sqrt(2)*9)
        g_pts4[n] = make_float4(points[n*3] * s, points[n*3+1] * s, points[n*3+2] * s, 0.f);
        g_nrm4[n] = make_float4(nuv[n*9], nuv[n*9+1], nuv[n*9+2], 0.f);
    }

    for (int k = tid; k < HDIM * IDIM; k += 512) {
        int h = k / IDIM, c = k % IDIM;
        sW1t[c * HDIM + h] = W1[k];
    }
    for (int k = tid; k < HDIM * HDIM; k += 512) {
        int h = k >> 5, c = k & 31;
        sW2t[c * HDIM + h] = W2[k];
    }
    if (tid < HDIM) { sb1[tid] = b1[tid]; sb2[tid] = b2[tid]; }
    __syncthreads();

    sX[wid][lane] = xin;
    __syncwarp();

    float a0 = 0.f, a1 = 0.f, a2 = 0.f, a3 = 0.f;
#pragma unroll
    for (int c = 0; c < IDIM; c += 4) {
        a0 = fmaf(sW1t[(c    ) * HDIM + lane], sX[wid][c    ], a0);
        a1 = fmaf(sW1t[(c + 1) * HDIM + lane], sX[wid][c + 1], a1);
        a2 = fmaf(sW1t[(c + 2) * HDIM + lane], sX[wid][c + 2], a2);
        a3 = fmaf(sW1t[(c + 3) * HDIM + lane], sX[wid][c + 3], a3);
    }
    float z1 = leakyf(((a0 + a1) + (a2 + a3)) + sb1[lane]);

    __syncwarp();
    sX[wid][lane] = z1;
    __syncwarp();

    a0 = a1 = a2 = a3 = 0.f;
#pragma unroll
    for (int c = 0; c < HDIM; c += 4) {
        a0 = fmaf(sW2t[(c    ) * HDIM + lane], sX[wid][c    ], a0);
        a1 = fmaf(sW2t[(c + 1) * HDIM + lane], sX[wid][c + 1], a1);
        a2 = fmaf(sW2t[(c + 2) * HDIM + lane], sX[wid][c + 2], a2);
        a3 = fmaf(sW2t[(c + 3) * HDIM + lane], sX[wid][c + 3], a3);
    }
    float out = leakyf(((a0 + a1) + (a2 + a3)) + sb2[lane]);
    g_z[n * HDIM + lane] = out;

    stats_tail(out, lane, wid, tid, sG, sGq, sFin, sFinQ, &sLast);
}

// ---------------- apply group norm (final output, float4) ----------------
__global__ void k_gnorm(const float* __restrict__ z, const float* __restrict__ gamma,
                        const float* __restrict__ beta, float* __restrict__ out) {
    int idx = blockIdx.x * blockDim.x + threadIdx.x;   // one float4
    if (idx >= NPTS * HDIM / 4) return;
    int q = idx & 7;
    int c0 = q * 4;
    float4 v = ((const float4*)z)[idx];
    int g0 = c0 >> 3, g1 = (c0 + 2) >> 3;
    float4 o;
    o.x = (v.x - g_stats[g0]) * g_stats[4 + g0] * gamma[c0]     + beta[c0];
    o.y = (v.y - g_stats[g0]) * g_stats[4 + g0] * gamma[c0 + 1] + beta[c0 + 1];
    o.z = (v.z - g_stats[g1]) * g_stats[4 + g1] * gamma[c0 + 2] + beta[c0 + 2];
    o.w = (v.w - g_stats[g1]) * g_stats[4 + g1] * gamma[c0 + 3] + beta[c0 + 3];
    ((float4*)out)[idx] = o;
}

// ---------------- pairwise interaction: folded frame (M=A1@u), dual packed dots ----------------
__global__ void __launch_bounds__(TILE_I, 2)
k_pair(const float* __restrict__ nuv,
       const float* __restrict__ A1, const float* __restrict__ B1,
       const float* __restrict__ A2, const float* __restrict__ B2,
       const float* __restrict__ gamma, const float* __restrict__ beta) {
    __shared__ ulonglong2 sDa[JCHUNK];   // {(pjx,njx),(pjy,njy)}
    __shared__ ulonglong2 sDb[JCHUNK];   // {(pjz,njz),(|pj|^2, 0)}
    __shared__ ulonglong2 sBa[JCHUNK];   // {(pjx,pjx),(pjy,pjy)}
    __shared__ ull        sBz[JCHUNK];   // (pjz,pjz)
    __shared__ __align__(16) float sF[JCHUNK][HDIM];
    __shared__ float smu[4], srs[4];

    int tid = threadIdx.x;
    int j0  = blockIdx.y * JCHUNK;
    int cnt = min(JCHUNK, NPTS - j0);

    if (tid < 4) { smu[tid] = g_stats[tid]; srs[tid] = g_stats[4 + tid]; }
    __syncthreads();   // smu/srs before sF fill

    for (int k = tid; k < cnt; k += TILE_I) {
        float4 pj = g_pts4[j0 + k];
        float4 nj = g_nrm4[j0 + k];
        float w2j = fmaf(pj.x, pj.x, fmaf(pj.y, pj.y, pj.z * pj.z));
        ulonglong2 da; da.x = pack2(pj.x, nj.x); da.y = pack2(pj.y, nj.y);
        ulonglong2 db; db.x = pack2(pj.z, nj.z); db.y = pack2(w2j, 0.f);
        ulonglong2 ba; ba.x = pack2(pj.x, pj.x); ba.y = pack2(pj.y, pj.y);
        sDa[k] = da; sDb[k] = db; sBa[k] = ba; sBz[k] = pack2(pj.z, pj.z);
    }
    for (int k = tid; k < cnt * (HDIM / 4); k += TILE_I) {
        int r = k >> 3, q = k & 7;
        float4 v = ((const float4*)g_z)[(j0 + r) * (HDIM / 4) + q];
        int c0 = q * 4;
        int g0 = c0 >> 3;
        float4 o;
        o.x = (v.x - smu[g0]) * srs[g0] * gamma[c0]     + beta[c0];
        o.y = (v.y - smu[g0]) * srs[g0] * gamma[c0 + 1] + beta[c0 + 1];
        int g1 = (c0 + 2) >> 3;
        o.z = (v.z - smu[g1]) * srs[g1] * gamma[c0 + 2] + beta[c0 + 2];
        o.w = (v.w - smu[g1]) * srs[g1] * gamma[c0 + 3] + beta[c0 + 3];
        ((float4*)sF)[k] = o;
    }
    __syncthreads();

    int half  = tid >> 6;
    int iloc  = tid & 63;
    int i     = blockIdx.x * 64 + iloc;
    int hbase = half * 16;

    float4 p4 = g_pts4[i];
    float4 n4 = g_nrm4[i];
    float ci = fmaf(p4.x, p4.x, fmaf(p4.y, p4.y, p4.z * p4.z));   // |p_i|^2
    ull pin0 = pack2(p4.x, n4.x), pin1 = pack2(p4.y, n4.y), pin2 = pack2(p4.z, n4.z);

    // M = A1 @ u_i (8x3), b1i = B1 - M . p_i  -> cut = M . p_j + b1i
    float M[24], b1i[8];
    {
        float u[9];
#pragma unroll
        for (int k = 0; k < 9; k++) u[k] = nuv[i * 9 + k];
#pragma unroll
        for (int k = 0; k < 8; k++) {
            float a0 = A1[k * 3], a1 = A1[k * 3 + 1], a2 = A1[k * 3 + 2];
#pragma unroll
            for (int c = 0; c < 3; c++)
                M[k * 3 + c] = fmaf(a0, u[c], fmaf(a1, u[3 + c], a2 * u[6 + c]));
            b1i[k] = B1[k] - (fmaf(M[k*3], p4.x, fmaf(M[k*3+1], p4.y, M[k*3+2] * p4.z)));
        }
    }
    ull m[12], b1ip[4];
#pragma unroll
    for (int comp = 0; comp < 3; comp++)
#pragma unroll
        for (int q = 0; q < 4; q++)
            m[comp * 4 + q] = pack2(M[(2*q) * 3 + comp], M[(2*q+1) * 3 + comp]);
#pragma unroll
    for (int q = 0; q < 4; q++) b1ip[q] = pack2(b1i[2*q], b1i[2*q+1]);

    // register-resident packed A2 slab: a2p[hp][c] = (A2[2hp][c], A2[2hp+1][c])
    ull a2p[64];
    ull b2p[8];
#pragma unroll
    for (int hp = 0; hp < 8; hp++) {
        int h0 = hbase + 2 * hp;
        float4 r0a = ((const float4*)A2)[h0 * 2];
        float4 r0b = ((const float4*)A2)[h0 * 2 + 1];
        float4 r1a = ((const float4*)A2)[(h0 + 1) * 2];
        float4 r1b = ((const float4*)A2)[(h0 + 1) * 2 + 1];
        a2p[hp * 8 + 0] = pack2(r0a.x, r1a.x);
        a2p[hp * 8 + 1] = pack2(r0a.y, r1a.y);
        a2p[hp * 8 + 2] = pack2(r0a.z, r1a.z);
        a2p[hp * 8 + 3] = pack2(r0a.w, r1a.w);
        a2p[hp * 8 + 4] = pack2(r0b.x, r1b.x);
        a2p[hp * 8 + 5] = pack2(r0b.y, r1b.y);
        a2p[hp * 8 + 6] = pack2(r0b.z, r1b.z);
        a2p[hp * 8 + 7] = pack2(r0b.w, r1b.w);
        b2p[hp] = pack2(B2[h0], B2[h0 + 1]);
    }

    ull acc[8];
#pragma unroll
    for (int hp = 0; hp < 8; hp++) acc[hp] = 0ull;

#pragma unroll 2
    for (int j = 0; j < cnt; j++) {
        ulonglong2 da = sDa[j];
        ulonglong2 db = sDb[j];
        ull dual = fma2(pin0, da.x, fma2(pin1, da.y, mul2(pin2, db.x)));
        float2 dd = unpack2(dual);
        float w2j = unpack2(db.y).x;
        float sq  = fmaf(-2.f, dd.x, ci + w2j);
        float t   = 2.f - dd.y;
        float w   = __expf(-(sq * t) * t);
        ull  w2   = pack2(w, w);

        ulonglong2 ba = sBa[j];
        ull bz = sBz[j];
        ull xcb[8];
#pragma unroll
        for (int q = 0; q < 4; q++) {
            ull s = fma2(m[q], ba.x, fma2(m[4 + q], ba.y, fma2(m[8 + q], bz, b1ip[q])));
            float2 v = unpack2(s);
            v.x = fmaxf(v.x, 0.f);
            v.y = fmaxf(v.y, 0.f);
            xcb[2*q]     = pack2(v.x, v.x);
            xcb[2*q + 1] = pack2(v.y, v.y);
        }

        const ulonglong2* frow = (const ulonglong2*)&sF[j][hbase];
#pragma unroll
        for (int q2 = 0; q2 < 4; q2++) {
            ulonglong2 fq = frow[q2];
#pragma unroll
            for (int hh = 0; hh < 2; hh++) {
                int hp = 2 * q2 + hh;
                ull wf = mul2(w2, hh ? fq.y : fq.x);
                const ull* ar = a2p + hp * 8;
                ull s = b2p[hp];
#pragma unroll
                for (int c = 0; c < 8; c++) s = fma2(ar[c], xcb[c], s);
                float2 v = unpack2(s);          // relu via 2x FMNMX (ALU pipe)
                v.x = fmaxf(v.x, 0.f);
                v.y = fmaxf(v.y, 0.f);
                acc[hp] = fma2(pack2(v.x, v.y), wf, acc[hp]);
            }
        }
    }

    ulonglong2* outp = (ulonglong2*)&g_partial[blockIdx.y][i * HDIM + hbase];
#pragma unroll
    for (int q = 0; q < 4; q++) {
        ulonglong2 v; v.x = acc[2*q]; v.y = acc[2*q+1];
        outp[q] = v;
    }
}

// ---------------- reduce(9) + net_out + fused group stats ----------------
__global__ void __launch_bounds__(512)
k_netout(const float* __restrict__ W1, const float* __restrict__ b1,
         const float* __restrict__ W2, const float* __restrict__ b2) {
    __shared__ float sW1t[HDIM * HDIM], sW2t[HDIM * HDIM], sb1[HDIM], sb2[HDIM];
    __shared__ float sX[16][HDIM];
    __shared__ float sG[16][4], sGq[16][4];
    __shared__ float sFin[512], sFinQ[512];
    __shared__ int   sLast;

    int tid  = threadIdx.x;
    int wid  = tid >> 5;
    int lane = tid & 31;
    int n    = blockIdx.x * 16 + wid;

    // issue the 9 partial-reduce loads FIRST (hide latency under weight staging)
    float xi = 0.f;
#pragma unroll
    for (int p = 0; p < JSPLIT; p++) xi += g_partial[p][n * HDIM + lane];

    for (int k = tid; k < HDIM * HDIM; k += 512) {
        int h = k >> 5, c = k & 31;
        sW1t[c * HDIM + h] = W1[k];
        sW2t[c * HDIM + h] = W2[k];
    }
    if (tid < HDIM) { sb1[tid] = b1[tid]; sb2[tid] = b2[tid]; }
    __syncthreads();

    sX[wid][lane] = xi;
    __syncwarp();

    float a0 = 0.f, a1 = 0.f, a2 = 0.f, a3 = 0.f;
#pragma unroll
    for (int c = 0; c < HDIM; c += 4) {
        a0 = fmaf(sW1t[(c    ) * HDIM + lane], sX[wid][c    ], a0);
        a1 = fmaf(sW1t[(c + 1) * HDIM + lane], sX[wid][c + 1], a1);
        a2 = fmaf(sW1t[(c + 2) * HDIM + lane], sX[wid][c + 2], a2);
        a3 = fmaf(sW1t[(c + 3) * HDIM + lane], sX[wid][c + 3], a3);
    }
    float z1 = leakyf(((a0 + a1) + (a2 + a3)) + sb1[lane]);

    __syncwarp();
    sX[wid][lane] = z1;
    __syncwarp();

    a0 = a1 = a2 = a3 = 0.f;
#pragma unroll
    for (int c = 0; c < HDIM; c += 4) {
        a0 = fmaf(sW2t[(c    ) * HDIM + lane], sX[wid][c    ], a0);
        a1 = fmaf(sW2t[(c + 1) * HDIM + lane], sX[wid][c + 1], a1);
        a2 = fmaf(sW2t[(c + 2) * HDIM + lane], sX[wid][c + 2], a2);
        a3 = fmaf(sW2t[(c + 3) * HDIM + lane], sX[wid][c + 3], a3);
    }
    float out = leakyf(((a0 + a1) + (a2 + a3)) + sb2[lane]);
    g_z[n * HDIM + lane] = out;

    stats_tail(out, lane, wid, tid, sG, sGq, sFin, sFinQ, &sLast);
}

// ---------------- launch ----------------
extern "C" void kernel_launch(void* const* d_in, const int* in_sizes, int n_in,
                              void* d_out, int out_size) {
    const float* points  = (const float*)d_in[0];
    const float* nuv     = (const float*)d_in[1];
    const float* feats   = (const float*)d_in[2];
    const float* W_in1   = (const float*)d_in[3];
    const float* b_in1   = (const float*)d_in[4];
    const float* W_in2   = (const float*)d_in[5];
    const float* b_in2   = (const float*)d_in[6];
    const float* g_in_w  = (const float*)d_in[7];
    const float* g_in_b  = (const float*)d_in[8];
    const float* A1      = (const float*)d_in[9];
    const float* A2      = (const float*)d_in[10];
    const float* W_out1  = (const float*)d_in[11];
    const float* b_out1  = (const float*)d_in[12];
    const float* W_out2  = (const float*)d_in[13];
    const float* b_out2  = (const float*)d_in[14];
    const float* g_out_w = (const float*)d_in[15];
    const float* g_out_b = (const float*)d_in[16];
    const float* B1      = (const float*)d_in[17];
    const float* B2      = (const float*)d_in[18];

    float* p_z;
    cudaGetSymbolAddress((void**)&p_z, g_z);

    k_netin<<<NETBLKS, 512>>>(points, nuv, feats, W_in1, b_in1, W_in2, b_in2);
    k_pair<<<dim3(NPTS / 64, JSPLIT), TILE_I>>>(nuv, A1, B1, A2, B2, g_in_w, g_in_b);
    k_netout<<<NETBLKS, 512>>>(W_out1, b_out1, W_out2, b_out2);
    k_gnorm<<<(NPTS * HDIM / 4) / 256, 256>>>(p_z, g_out_w, g_out_b, (float*)d_out);
}

// round 16
// speedup vs baseline: 1.9024x; 1.0030x over previous
#include <cuda_runtime.h>
#include <math.h>

#define NPTS   2048
#define IDIM   16
#define HDIM   32
#define JSPLIT 9
#define JCHUNK 228          // 8*228 + 224 = 2048
#define TILE_I 128
#define NETBLKS (NPTS / 16) // 128  (<= 148 SMs: all co-resident -> spin barrier is safe)

typedef unsigned long long ull;

// ---------------- device scratch ----------------
__device__ float4 g_pts4[NPTS];
__device__ float4 g_nrm4[NPTS];
__device__ float  g_z   [NPTS * HDIM];
__device__ float  g_partial[JSPLIT][NPTS * HDIM];
__device__ float  g_stats[8];            // mu[0..3], rstd[4..7]
__device__ float  g_bs[NETBLKS][4];      // per-block group sums
__device__ float  g_bq[NETBLKS][4];      // per-block group sumsq
__device__ unsigned g_cnt = 0;           // last-block counter (self-resetting)
__device__ unsigned g_epoch = 0;         // monotonic stats-ready epoch (replay-safe)

__device__ __forceinline__ float leakyf(float x) { return x >= 0.f ? x : 0.2f * x; }

// ---------------- packed f32x2 (native 64-bit regs, sm_103a) ----------------
__device__ __forceinline__ ull fma2(ull a, ull b, ull c) {
    ull d; asm("fma.rn.f32x2 %0, %1, %2, %3;" : "=l"(d) : "l"(a), "l"(b), "l"(c)); return d;
}
__device__ __forceinline__ ull mul2(ull a, ull b) {
    ull d; asm("mul.rn.f32x2 %0, %1, %2;" : "=l"(d) : "l"(a), "l"(b)); return d;
}
__device__ __forceinline__ ull pack2(float lo, float hi) {
    ull d; asm("mov.b64 %0, {%1, %2};" : "=l"(d) : "f"(lo), "f"(hi)); return d;
}
__device__ __forceinline__ float2 unpack2(ull a) {
    float2 v; asm("mov.b64 {%0, %1}, %2;" : "=f"(v.x), "=f"(v.y) : "l"(a)); return v;
}

// ---------------- fused block-level group stats + last-block finalize ----------------
// val: this thread's output value (channel = lane, group = lane>>3). grid must be NETBLKS.
__device__ __forceinline__ void stats_tail(float val, int lane, int wid, int tid,
                                           float (*sG)[4], float (*sGq)[4],
                                           float* sFin, float* sFinQ, int* sLast) {
    float s = val, q = val * val;
#pragma unroll
    for (int off = 4; off; off >>= 1) {
        s += __shfl_down_sync(0xffffffffu, s, off, 8);
        q += __shfl_down_sync(0xffffffffu, q, off, 8);
    }
    if ((lane & 7) == 0) { sG[wid][lane >> 3] = s; sGq[wid][lane >> 3] = q; }
    __syncthreads();
    if (tid == 0) {
#pragma unroll
        for (int g = 0; g < 4; g++) {
            float S = 0.f, Q = 0.f;
            for (int w = 0; w < 16; w++) { S += sG[w][g]; Q += sGq[w][g]; }
            g_bs[blockIdx.x][g] = S; g_bq[blockIdx.x][g] = Q;
        }
        __threadfence();
        unsigned old = atomicAdd(&g_cnt, 1u);
        *sLast = (old == NETBLKS - 1) ? 1 : 0;
    }
    __syncthreads();
    if (*sLast) {
        int b = tid & 127, g = tid >> 7;   // 512 threads cover 128 blocks x 4 groups
        sFin[g * 128 + b]  = g_bs[b][g];
        sFinQ[g * 128 + b] = g_bq[b][g];
        __syncthreads();
        for (int off = 64; off >= 1; off >>= 1) {
            if (b < off) {
                sFin[g * 128 + b]  += sFin[g * 128 + b + off];
                sFinQ[g * 128 + b] += sFinQ[g * 128 + b + off];
            }
            __syncthreads();
        }
        if (tid < 4) {
            double S = (double)sFin[tid * 128];
            double Q = (double)sFinQ[tid * 128];
            double cntd = (double)NPTS * 8.0;
            double mu = S / cntd;
            double var = Q / cntd - mu * mu;
            g_stats[tid]     = (float)mu;
            g_stats[4 + tid] = (float)(1.0 / sqrt(var + 1e-5));
        }
        if (tid == 0) g_cnt = 0;           // reset for next use / replay
    }
}

// ---------------- net_in + prep + fused group stats ----------------
__global__ void __launch_bounds__(512)
k_netin(const float* __restrict__ points, const float* __restrict__ nuv,
        const float* __restrict__ x,
        const float* __restrict__ W1, const float* __restrict__ b1,
        const float* __restrict__ W2, const float* __restrict__ b2) {
    __shared__ float sW1t[IDIM * HDIM];   // [c][h]
    __shared__ float sW2t[HDIM * HDIM];   // [c][h]
    __shared__ float sb1[HDIM], sb2[HDIM];
    __shared__ float sX[16][HDIM];
    __shared__ float sG[16][4], sGq[16][4];
    __shared__ float sFin[512], sFinQ[512];
    __shared__ int   sLast;

    int tid  = threadIdx.x;
    int wid  = tid >> 5;
    int lane = tid & 31;
    int n    = blockIdx.x * 16 + wid;

    // issue input loads FIRST (hide latency under weight staging)
    float xin = (lane < IDIM) ? x[n * IDIM + lane] : 0.f;

    if (lane == 0) {
        const float s = 0.07856742013183862f;  // 1/(sqrt(2)*9)
        g_pts4[n] = make_float4(points[n*3] * s, points[n*3+1] * s, points[n*3+2] * s, 0.f);
        g_nrm4[n] = make_float4(nuv[n*9], nuv[n*9+1], nuv[n*9+2], 0.f);
    }

    for (int k = tid; k < HDIM * IDIM; k += 512) {
        int h = k / IDIM, c = k % IDIM;
        sW1t[c * HDIM + h] = W1[k];
    }
    for (int k = tid; k < HDIM * HDIM; k += 512) {
        int h = k >> 5, c = k & 31;
        sW2t[c * HDIM + h] = W2[k];
    }
    if (tid < HDIM) { sb1[tid] = b1[tid]; sb2[tid] = b2[tid]; }
    __syncthreads();

    sX[wid][lane] = xin;
    __syncwarp();

    float a0 = 0.f, a1 = 0.f, a2 = 0.f, a3 = 0.f;
#pragma unroll
    for (int c = 0; c < IDIM; c += 4) {
        a0 = fmaf(sW1t[(c    ) * HDIM + lane], sX[wid][c    ], a0);
        a1 = fmaf(sW1t[(c + 1) * HDIM + lane], sX[wid][c + 1], a1);
        a2 = fmaf(sW1t[(c + 2) * HDIM + lane], sX[wid][c + 2], a2);
        a3 = fmaf(sW1t[(c + 3) * HDIM + lane], sX[wid][c + 3], a3);
    }
    float z1 = leakyf(((a0 + a1) + (a2 + a3)) + sb1[lane]);

    __syncwarp();
    sX[wid][lane] = z1;
    __syncwarp();

    a0 = a1 = a2 = a3 = 0.f;
#pragma unroll
    for (int c = 0; c < HDIM; c += 4) {
        a0 = fmaf(sW2t[(c    ) * HDIM + lane], sX[wid][c    ], a0);
        a1 = fmaf(sW2t[(c + 1) * HDIM + lane], sX[wid][c + 1], a1);
        a2 = fmaf(sW2t[(c + 2) * HDIM + lane], sX[wid][c + 2], a2);
        a3 = fmaf(sW2t[(c + 3) * HDIM + lane], sX[wid][c + 3], a3);
    }
    float out = leakyf(((a0 + a1) + (a2 + a3)) + sb2[lane]);
    g_z[n * HDIM + lane] = out;

    stats_tail(out, lane, wid, tid, sG, sGq, sFin, sFinQ, &sLast);
}

// ---------------- pairwise interaction: folded frame (M=A1@u), dual packed dots ----------------
__global__ void __launch_bounds__(TILE_I, 2)
k_pair(const float* __restrict__ nuv,
       const float* __restrict__ A1, const float* __restrict__ B1,
       const float* __restrict__ A2, const float* __restrict__ B2,
       const float* __restrict__ gamma, const float* __restrict__ beta) {
    __shared__ ulonglong2 sDa[JCHUNK];   // {(pjx,njx),(pjy,njy)}
    __shared__ ulonglong2 sDb[JCHUNK];   // {(pjz,njz),(|pj|^2, 0)}
    __shared__ ulonglong2 sBa[JCHUNK];   // {(pjx,pjx),(pjy,pjy)}
    __shared__ ull        sBz[JCHUNK];   // (pjz,pjz)
    __shared__ __align__(16) float sF[JCHUNK][HDIM];
    __shared__ float smu[4], srs[4];

    int tid = threadIdx.x;
    int j0  = blockIdx.y * JCHUNK;
    int cnt = min(JCHUNK, NPTS - j0);

    if (tid < 4) { smu[tid] = g_stats[tid]; srs[tid] = g_stats[4 + tid]; }
    __syncthreads();   // smu/srs before sF fill

    for (int k = tid; k < cnt; k += TILE_I) {
        float4 pj = g_pts4[j0 + k];
        float4 nj = g_nrm4[j0 + k];
        float w2j = fmaf(pj.x, pj.x, fmaf(pj.y, pj.y, pj.z * pj.z));
        ulonglong2 da; da.x = pack2(pj.x, nj.x); da.y = pack2(pj.y, nj.y);
        ulonglong2 db; db.x = pack2(pj.z, nj.z); db.y = pack2(w2j, 0.f);
        ulonglong2 ba; ba.x = pack2(pj.x, pj.x); ba.y = pack2(pj.y, pj.y);
        sDa[k] = da; sDb[k] = db; sBa[k] = ba; sBz[k] = pack2(pj.z, pj.z);
    }
    for (int k = tid; k < cnt * (HDIM / 4); k += TILE_I) {
        int r = k >> 3, q = k & 7;
        float4 v = ((const float4*)g_z)[(j0 + r) * (HDIM / 4) + q];
        int c0 = q * 4;
        int g0 = c0 >> 3;
        float4 o;
        o.x = (v.x - smu[g0]) * srs[g0] * gamma[c0]     + beta[c0];
        o.y = (v.y - smu[g0]) * srs[g0] * gamma[c0 + 1] + beta[c0 + 1];
        int g1 = (c0 + 2) >> 3;
        o.z = (v.z - smu[g1]) * srs[g1] * gamma[c0 + 2] + beta[c0 + 2];
        o.w = (v.w - smu[g1]) * srs[g1] * gamma[c0 + 3] + beta[c0 + 3];
        ((float4*)sF)[k] = o;
    }
    __syncthreads();

    int half  = tid >> 6;
    int iloc  = tid & 63;
    int i     = blockIdx.x * 64 + iloc;
    int hbase = half * 16;

    float4 p4 = g_pts4[i];
    float4 n4 = g_nrm4[i];
    float ci = fmaf(p4.x, p4.x, fmaf(p4.y, p4.y, p4.z * p4.z));   // |p_i|^2
    ull pin0 = pack2(p4.x, n4.x), pin1 = pack2(p4.y, n4.y), pin2 = pack2(p4.z, n4.z);

    // M = A1 @ u_i (8x3), b1i = B1 - M . p_i  -> cut = M . p_j + b1i
    float M[24], b1i[8];
    {
        float u[9];
#pragma unroll
        for (int k = 0; k < 9; k++) u[k] = nuv[i * 9 + k];
#pragma unroll
        for (int k = 0; k < 8; k++) {
            float a0 = A1[k * 3], a1 = A1[k * 3 + 1], a2 = A1[k * 3 + 2];
#pragma unroll
            for (int c = 0; c < 3; c++)
                M[k * 3 + c] = fmaf(a0, u[c], fmaf(a1, u[3 + c], a2 * u[6 + c]));
            b1i[k] = B1[k] - (fmaf(M[k*3], p4.x, fmaf(M[k*3+1], p4.y, M[k*3+2] * p4.z)));
        }
    }
    ull m[12], b1ip[4];
#pragma unroll
    for (int comp = 0; comp < 3; comp++)
#pragma unroll
        for (int q = 0; q < 4; q++)
            m[comp * 4 + q] = pack2(M[(2*q) * 3 + comp], M[(2*q+1) * 3 + comp]);
#pragma unroll
    for (int q = 0; q < 4; q++) b1ip[q] = pack2(b1i[2*q], b1i[2*q+1]);

    // register-resident packed A2 slab: a2p[hp][c] = (A2[2hp][c], A2[2hp+1][c])
    ull a2p[64];
    ull b2p[8];
#pragma unroll
    for (int hp = 0; hp < 8; hp++) {
        int h0 = hbase + 2 * hp;
        float4 r0a = ((const float4*)A2)[h0 * 2];
        float4 r0b = ((const float4*)A2)[h0 * 2 + 1];
        float4 r1a = ((const float4*)A2)[(h0 + 1) * 2];
        float4 r1b = ((const float4*)A2)[(h0 + 1) * 2 + 1];
        a2p[hp * 8 + 0] = pack2(r0a.x, r1a.x);
        a2p[hp * 8 + 1] = pack2(r0a.y, r1a.y);
        a2p[hp * 8 + 2] = pack2(r0a.z, r1a.z);
        a2p[hp * 8 + 3] = pack2(r0a.w, r1a.w);
        a2p[hp * 8 + 4] = pack2(r0b.x, r1b.x);
        a2p[hp * 8 + 5] = pack2(r0b.y, r1b.y);
        a2p[hp * 8 + 6] = pack2(r0b.z, r1b.z);
        a2p[hp * 8 + 7] = pack2(r0b.w, r1b.w);
        b2p[hp] = pack2(B2[h0], B2[h0 + 1]);
    }

    ull acc[8];
#pragma unroll
    for (int hp = 0; hp < 8; hp++) acc[hp] = 0ull;

#pragma unroll 2
    for (int j = 0; j < cnt; j++) {
        ulonglong2 da = sDa[j];
        ulonglong2 db = sDb[j];
        ull dual = fma2(pin0, da.x, fma2(pin1, da.y, mul2(pin2, db.x)));
        float2 dd = unpack2(dual);
        float w2j = unpack2(db.y).x;
        float sq  = fmaf(-2.f, dd.x, ci + w2j);
        float t   = 2.f - dd.y;
        float w   = __expf(-(sq * t) * t);
        ull  w2   = pack2(w, w);

        ulonglong2 ba = sBa[j];
        ull bz = sBz[j];
        ull xcb[8];
#pragma unroll
        for (int q = 0; q < 4; q++) {
            ull s = fma2(m[q], ba.x, fma2(m[4 + q], ba.y, fma2(m[8 + q], bz, b1ip[q])));
            float2 v = unpack2(s);
            v.x = fmaxf(v.x, 0.f);
            v.y = fmaxf(v.y, 0.f);
            xcb[2*q]     = pack2(v.x, v.x);
            xcb[2*q + 1] = pack2(v.y, v.y);
        }

        const ulonglong2* frow = (const ulonglong2*)&sF[j][hbase];
#pragma unroll
        for (int q2 = 0; q2 < 4; q2++) {
            ulonglong2 fq = frow[q2];
#pragma unroll
            for (int hh = 0; hh < 2; hh++) {
                int hp = 2 * q2 + hh;
                ull wf = mul2(w2, hh ? fq.y : fq.x);
                const ull* ar = a2p + hp * 8;
                ull s = b2p[hp];
#pragma unroll
                for (int c = 0; c < 8; c++) s = fma2(ar[c], xcb[c], s);
                float2 v = unpack2(s);          // relu via 2x FMNMX (ALU pipe)
                v.x = fmaxf(v.x, 0.f);
                v.y = fmaxf(v.y, 0.f);
                acc[hp] = fma2(pack2(v.x, v.y), wf, acc[hp]);
            }
        }
    }

    ulonglong2* outp = (ulonglong2*)&g_partial[blockIdx.y][i * HDIM + hbase];
#pragma unroll
    for (int q = 0; q < 4; q++) {
        ulonglong2 v; v.x = acc[2*q]; v.y = acc[2*q+1];
        outp[q] = v;
    }
}

// ---------------- reduce(9) + net_out + stats + FINAL GNORM (grid-spin) ----------------
__global__ void __launch_bounds__(512)
k_netout(const float* __restrict__ W1, const float* __restrict__ b1,
         const float* __restrict__ W2, const float* __restrict__ b2,
         const float* __restrict__ gamma, const float* __restrict__ beta,
         float* __restrict__ dout) {
    __shared__ float sW1t[HDIM * HDIM], sW2t[HDIM * HDIM], sb1[HDIM], sb2[HDIM];
    __shared__ float sX[16][HDIM];
    __shared__ float sG[16][4], sGq[16][4];
    __shared__ float sFin[512], sFinQ[512];
    __shared__ int   sLast;
    __shared__ unsigned sEpoch0;

    int tid  = threadIdx.x;
    int wid  = tid >> 5;
    int lane = tid & 31;
    int n    = blockIdx.x * 16 + wid;

    // snapshot the epoch BEFORE this block's stats arrival (ordering proof:
    // increment requires ALL blocks to arrive; our arrival is after this read)
    if (tid == 0) sEpoch0 = *(volatile unsigned*)&g_epoch;

    // issue the 9 partial-reduce loads FIRST (hide latency under weight staging)
    float xi = 0.f;
#pragma unroll
    for (int p = 0; p < JSPLIT; p++) xi += g_partial[p][n * HDIM + lane];

    for (int k = tid; k < HDIM * HDIM; k += 512) {
        int h = k >> 5, c = k & 31;
        sW1t[c * HDIM + h] = W1[k];
        sW2t[c * HDIM + h] = W2[k];
    }
    if (tid < HDIM) { sb1[tid] = b1[tid]; sb2[tid] = b2[tid]; }
    __syncthreads();

    sX[wid][lane] = xi;
    __syncwarp();

    float a0 = 0.f, a1 = 0.f, a2 = 0.f, a3 = 0.f;
#pragma unroll
    for (int c = 0; c < HDIM; c += 4) {
        a0 = fmaf(sW1t[(c    ) * HDIM + lane], sX[wid][c    ], a0);
        a1 = fmaf(sW1t[(c + 1) * HDIM + lane], sX[wid][c + 1], a1);
        a2 = fmaf(sW1t[(c + 2) * HDIM + lane], sX[wid][c + 2], a2);
        a3 = fmaf(sW1t[(c + 3) * HDIM + lane], sX[wid][c + 3], a3);
    }
    float z1 = leakyf(((a0 + a1) + (a2 + a3)) + sb1[lane]);

    __syncwarp();
    sX[wid][lane] = z1;
    __syncwarp();

    a0 = a1 = a2 = a3 = 0.f;
#pragma unroll
    for (int c = 0; c < HDIM; c += 4) {
        a0 = fmaf(sW2t[(c    ) * HDIM + lane], sX[wid][c    ], a0);
        a1 = fmaf(sW2t[(c + 1) * HDIM + lane], sX[wid][c + 1], a1);
        a2 = fmaf(sW2t[(c + 2) * HDIM + lane], sX[wid][c + 2], a2);
        a3 = fmaf(sW2t[(c + 3) * HDIM + lane], sX[wid][c + 3], a3);
    }
    float out = leakyf(((a0 + a1) + (a2 + a3)) + sb2[lane]);

    stats_tail(out, lane, wid, tid, sG, sGq, sFin, sFinQ, &sLast);

    __syncthreads();
    if (sLast && tid == 0) {
        __threadfence();                       // publish g_stats before epoch bump
        atomicAdd((unsigned*)&g_epoch, 1u);
    }
    // grid-wide wait: all 128 blocks are co-resident (grid <= SM count)
    if (tid == 0) {
        while (*(volatile unsigned*)&g_epoch == sEpoch0) { }
    }
    __syncthreads();
    __threadfence();                           // acquire side

    // final group norm, values still in registers
    int g = lane >> 3;
    float mu = g_stats[g], rs = g_stats[4 + g];
    dout[n * HDIM + lane] = (out - mu) * rs * gamma[lane] + beta[lane];
}

// ---------------- launch ----------------
extern "C" void kernel_launch(void* const* d_in, const int* in_sizes, int n_in,
                              void* d_out, int out_size) {
    const float* points  = (const float*)d_in[0];
    const float* nuv     = (const float*)d_in[1];
    const float* feats   = (const float*)d_in[2];
    const float* W_in1   = (const float*)d_in[3];
    const float* b_in1   = (const float*)d_in[4];
    const float* W_in2   = (const float*)d_in[5];
    const float* b_in2   = (const float*)d_in[6];
    const float* g_in_w  = (const float*)d_in[7];
    const float* g_in_b  = (const float*)d_in[8];
    const float* A1      = (const float*)d_in[9];
    const float* A2      = (const float*)d_in[10];
    const float* W_out1  = (const float*)d_in[11];
    const float* b_out1  = (const float*)d_in[12];
    const float* W_out2  = (const float*)d_in[13];
    const float* b_out2  = (const float*)d_in[14];
    const float* g_out_w = (const float*)d_in[15];
    const float* g_out_b = (const float*)d_in[16];
    const float* B1      = (const float*)d_in[17];
    const float* B2      = (const float*)d_in[18];

    k_netin<<<NETBLKS, 512>>>(points, nuv, feats, W_in1, b_in1, W_in2, b_in2);
    k_pair<<<dim3(NPTS / 64, JSPLIT), TILE_I>>>(nuv, A1, B1, A2, B2, g_in_w, g_in_b);
    k_netout<<<NETBLKS, 512>>>(W_out1, b_out1, W_out2, b_out2,
                               g_out_w, g_out_b, (float*)d_out);
}

// round 17
// speedup vs baseline: 1.9031x; 1.0004x over previous
#include <cuda_runtime.h>
#include <math.h>

#define NPTS   2048
#define IDIM   16
#define HDIM   32
#define JSPLIT 9
#define JCHUNK 228          // 8*228 + 224 = 2048
#define TILE_I 128
#define NETBLKS (NPTS / 16) // 128  (<= 148 SMs: all co-resident -> spin barrier is safe)

typedef unsigned long long ull;

// ---------------- device scratch ----------------
__device__ float4 g_pts4[NPTS];
__device__ float4 g_nrm4[NPTS];
__device__ float  g_z   [NPTS * HDIM];
__device__ float  g_partial[JSPLIT][NPTS * HDIM];
__device__ float  g_stats[8];            // mu[0..3], rstd[4..7] (netout only)
__device__ float  g_bs[NETBLKS][4];      // per-block group sums   (netin partials)
__device__ float  g_bq[NETBLKS][4];      // per-block group sumsq
__device__ unsigned g_cnt = 0;           // last-block counter (netout only, self-resetting)
__device__ unsigned g_epoch = 0;         // monotonic stats-ready epoch (replay-safe)

__device__ __forceinline__ float leakyf(float x) { return x >= 0.f ? x : 0.2f * x; }

// ---------------- packed f32x2 (native 64-bit regs, sm_103a) ----------------
__device__ __forceinline__ ull fma2(ull a, ull b, ull c) {
    ull d; asm("fma.rn.f32x2 %0, %1, %2, %3;" : "=l"(d) : "l"(a), "l"(b), "l"(c)); return d;
}
__device__ __forceinline__ ull mul2(ull a, ull b) {
    ull d; asm("mul.rn.f32x2 %0, %1, %2;" : "=l"(d) : "l"(a), "l"(b)); return d;
}
__device__ __forceinline__ ull pack2(float lo, float hi) {
    ull d; asm("mov.b64 %0, {%1, %2};" : "=l"(d) : "f"(lo), "f"(hi)); return d;
}
__device__ __forceinline__ float2 unpack2(ull a) {
    float2 v; asm("mov.b64 {%0, %1}, %2;" : "=f"(v.x), "=f"(v.y) : "l"(a)); return v;
}

// ---------------- block-level group partials (no finalize, no atomics) ----------------
__device__ __forceinline__ void stats_partials(float val, int lane, int wid, int tid,
                                               float (*sG)[4], float (*sGq)[4]) {
    float s = val, q = val * val;
#pragma unroll
    for (int off = 4; off; off >>= 1) {
        s += __shfl_down_sync(0xffffffffu, s, off, 8);
        q += __shfl_down_sync(0xffffffffu, q, off, 8);
    }
    if ((lane & 7) == 0) { sG[wid][lane >> 3] = s; sGq[wid][lane >> 3] = q; }
    __syncthreads();
    if (tid < 4) {
        float S = 0.f, Q = 0.f;
#pragma unroll
        for (int w = 0; w < 16; w++) { S += sG[w][tid]; Q += sGq[w][tid]; }
        g_bs[blockIdx.x][tid] = S; g_bq[blockIdx.x][tid] = Q;
    }
}

// ---------------- net_in + prep + per-block group partials ----------------
__global__ void __launch_bounds__(512)
k_netin(const float* __restrict__ points, const float* __restrict__ nuv,
        const float* __restrict__ x,
        const float* __restrict__ W1, const float* __restrict__ b1,
        const float* __restrict__ W2, const float* __restrict__ b2) {
    __shared__ float sW1t[IDIM * HDIM];   // [c][h]
    __shared__ float sW2t[HDIM * HDIM];   // [c][h]
    __shared__ float sb1[HDIM], sb2[HDIM];
    __shared__ float sX[16][HDIM];
    __shared__ float sG[16][4], sGq[16][4];

    int tid  = threadIdx.x;
    int wid  = tid >> 5;
    int lane = tid & 31;
    int n    = blockIdx.x * 16 + wid;

    // issue input loads FIRST (hide latency under weight staging)
    float xin = (lane < IDIM) ? x[n * IDIM + lane] : 0.f;

    if (lane == 0) {
        const float s = 0.07856742013183862f;  // 1/(sqrt(2)*9)
        g_pts4[n] = make_float4(points[n*3] * s, points[n*3+1] * s, points[n*3+2] * s, 0.f);
        g_nrm4[n] = make_float4(nuv[n*9], nuv[n*9+1], nuv[n*9+2], 0.f);
    }

    for (int k = tid; k < HDIM * IDIM; k += 512) {
        int h = k / IDIM, c = k % IDIM;
        sW1t[c * HDIM + h] = W1[k];
    }
    for (int k = tid; k < HDIM * HDIM; k += 512) {
        int h = k >> 5, c = k & 31;
        sW2t[c * HDIM + h] = W2[k];
    }
    if (tid < HDIM) { sb1[tid] = b1[tid]; sb2[tid] = b2[tid]; }
    __syncthreads();

    sX[wid][lane] = xin;
    __syncwarp();

    float a0 = 0.f, a1 = 0.f, a2 = 0.f, a3 = 0.f;
#pragma unroll
    for (int c = 0; c < IDIM; c += 4) {
        a0 = fmaf(sW1t[(c    ) * HDIM + lane], sX[wid][c    ], a0);
        a1 = fmaf(sW1t[(c + 1) * HDIM + lane], sX[wid][c + 1], a1);
        a2 = fmaf(sW1t[(c + 2) * HDIM + lane], sX[wid][c + 2], a2);
        a3 = fmaf(sW1t[(c + 3) * HDIM + lane], sX[wid][c + 3], a3);
    }
    float z1 = leakyf(((a0 + a1) + (a2 + a3)) + sb1[lane]);

    __syncwarp();
    sX[wid][lane] = z1;
    __syncwarp();

    a0 = a1 = a2 = a3 = 0.f;
#pragma unroll
    for (int c = 0; c < HDIM; c += 4) {
        a0 = fmaf(sW2t[(c    ) * HDIM + lane], sX[wid][c    ], a0);
        a1 = fmaf(sW2t[(c + 1) * HDIM + lane], sX[wid][c + 1], a1);
        a2 = fmaf(sW2t[(c + 2) * HDIM + lane], sX[wid][c + 2], a2);
        a3 = fmaf(sW2t[(c + 3) * HDIM + lane], sX[wid][c + 3], a3);
    }
    float out = leakyf(((a0 + a1) + (a2 + a3)) + sb2[lane]);
    g_z[n * HDIM + lane] = out;

    // per-block partials only; finalize happens redundantly in k_pair
    stats_partials(out, lane, wid, tid, sG, sGq);
}

// ---------------- pairwise interaction: folded frame, dual packed dots ----------------
// Each block redundantly finalizes the group stats from netin's 128x4 partials.
__global__ void __launch_bounds__(TILE_I, 2)
k_pair(const float* __restrict__ nuv,
       const float* __restrict__ A1, const float* __restrict__ B1,
       const float* __restrict__ A2, const float* __restrict__ B2,
       const float* __restrict__ gamma, const float* __restrict__ beta) {
    __shared__ ulonglong2 sDa[JCHUNK];   // {(pjx,njx),(pjy,njy)}
    __shared__ ulonglong2 sDb[JCHUNK];   // {(pjz,njz),(|pj|^2, 0)}
    __shared__ ulonglong2 sBa[JCHUNK];   // {(pjx,pjx),(pjy,pjy)}
    __shared__ ull        sBz[JCHUNK];   // (pjz,pjz)
    __shared__ __align__(16) float sF[JCHUNK][HDIM];
    __shared__ float sRedS[4][TILE_I], sRedQ[4][TILE_I];
    __shared__ float smu[4], srs[4];

    int tid = threadIdx.x;
    int j0  = blockIdx.y * JCHUNK;
    int cnt = min(JCHUNK, NPTS - j0);

    // --- finalize stats from netin partials (deterministic, same in every block) ---
#pragma unroll
    for (int g = 0; g < 4; g++) {
        sRedS[g][tid] = g_bs[tid][g];
        sRedQ[g][tid] = g_bq[tid][g];
    }
    __syncthreads();
    for (int off = 64; off >= 1; off >>= 1) {
        if (tid < off) {
#pragma unroll
            for (int g = 0; g < 4; g++) {
                sRedS[g][tid] += sRedS[g][tid + off];
                sRedQ[g][tid] += sRedQ[g][tid + off];
            }
        }
        __syncthreads();
    }
    if (tid < 4) {
        double S = (double)sRedS[tid][0];
        double Q = (double)sRedQ[tid][0];
        double cntd = (double)NPTS * 8.0;
        double mu = S / cntd;
        double var = Q / cntd - mu * mu;
        smu[tid] = (float)mu;
        srs[tid] = (float)(1.0 / sqrt(var + 1e-5));
    }
    __syncthreads();

    for (int k = tid; k < cnt; k += TILE_I) {
        float4 pj = g_pts4[j0 + k];
        float4 nj = g_nrm4[j0 + k];
        float w2j = fmaf(pj.x, pj.x, fmaf(pj.y, pj.y, pj.z * pj.z));
        ulonglong2 da; da.x = pack2(pj.x, nj.x); da.y = pack2(pj.y, nj.y);
        ulonglong2 db; db.x = pack2(pj.z, nj.z); db.y = pack2(w2j, 0.f);
        ulonglong2 ba; ba.x = pack2(pj.x, pj.x); ba.y = pack2(pj.y, pj.y);
        sDa[k] = da; sDb[k] = db; sBa[k] = ba; sBz[k] = pack2(pj.z, pj.z);
    }
    for (int k = tid; k < cnt * (HDIM / 4); k += TILE_I) {
        int r = k >> 3, q = k & 7;
        float4 v = ((const float4*)g_z)[(j0 + r) * (HDIM / 4) + q];
        int c0 = q * 4;
        int g0 = c0 >> 3;
        float4 o;
        o.x = (v.x - smu[g0]) * srs[g0] * gamma[c0]     + beta[c0];
        o.y = (v.y - smu[g0]) * srs[g0] * gamma[c0 + 1] + beta[c0 + 1];
        int g1 = (c0 + 2) >> 3;
        o.z = (v.z - smu[g1]) * srs[g1] * gamma[c0 + 2] + beta[c0 + 2];
        o.w = (v.w - smu[g1]) * srs[g1] * gamma[c0 + 3] + beta[c0 + 3];
        ((float4*)sF)[k] = o;
    }
    __syncthreads();

    int half  = tid >> 6;
    int iloc  = tid & 63;
    int i     = blockIdx.x * 64 + iloc;
    int hbase = half * 16;

    float4 p4 = g_pts4[i];
    float4 n4 = g_nrm4[i];
    float ci = fmaf(p4.x, p4.x, fmaf(p4.y, p4.y, p4.z * p4.z));   // |p_i|^2
    ull pin0 = pack2(p4.x, n4.x), pin1 = pack2(p4.y, n4.y), pin2 = pack2(p4.z, n4.z);

    // M = A1 @ u_i (8x3), b1i = B1 - M . p_i  -> cut = M . p_j + b1i
    float M[24], b1i[8];
    {
        float u[9];
#pragma unroll
        for (int k = 0; k < 9; k++) u[k] = nuv[i * 9 + k];
#pragma unroll
        for (int k = 0; k < 8; k++) {
            float a0 = A1[k * 3], a1 = A1[k * 3 + 1], a2 = A1[k * 3 + 2];
#pragma unroll
            for (int c = 0; c < 3; c++)
                M[k * 3 + c] = fmaf(a0, u[c], fmaf(a1, u[3 + c], a2 * u[6 + c]));
            b1i[k] = B1[k] - (fmaf(M[k*3], p4.x, fmaf(M[k*3+1], p4.y, M[k*3+2] * p4.z)));
        }
    }
    ull m[12], b1ip[4];
#pragma unroll
    for (int comp = 0; comp < 3; comp++)
#pragma unroll
        for (int q = 0; q < 4; q++)
            m[comp * 4 + q] = pack2(M[(2*q) * 3 + comp], M[(2*q+1) * 3 + comp]);
#pragma unroll
    for (int q = 0; q < 4; q++) b1ip[q] = pack2(b1i[2*q], b1i[2*q+1]);

    // register-resident packed A2 slab: a2p[hp][c] = (A2[2hp][c], A2[2hp+1][c])
    ull a2p[64];
    ull b2p[8];
#pragma unroll
    for (int hp = 0; hp < 8; hp++) {
        int h0 = hbase + 2 * hp;
        float4 r0a = ((const float4*)A2)[h0 * 2];
        float4 r0b = ((const float4*)A2)[h0 * 2 + 1];
        float4 r1a = ((const float4*)A2)[(h0 + 1) * 2];
        float4 r1b = ((const float4*)A2)[(h0 + 1) * 2 + 1];
        a2p[hp * 8 + 0] = pack2(r0a.x, r1a.x);
        a2p[hp * 8 + 1] = pack2(r0a.y, r1a.y);
        a2p[hp * 8 + 2] = pack2(r0a.z, r1a.z);
        a2p[hp * 8 + 3] = pack2(r0a.w, r1a.w);
        a2p[hp * 8 + 4] = pack2(r0b.x, r1b.x);
        a2p[hp * 8 + 5] = pack2(r0b.y, r1b.y);
        a2p[hp * 8 + 6] = pack2(r0b.z, r1b.z);
        a2p[hp * 8 + 7] = pack2(r0b.w, r1b.w);
        b2p[hp] = pack2(B2[h0], B2[h0 + 1]);
    }

    ull acc[8];
#pragma unroll
    for (int hp = 0; hp < 8; hp++) acc[hp] = 0ull;

#pragma unroll 2
    for (int j = 0; j < cnt; j++) {
        ulonglong2 da = sDa[j];
        ulonglong2 db = sDb[j];
        ull dual = fma2(pin0, da.x, fma2(pin1, da.y, mul2(pin2, db.x)));
        float2 dd = unpack2(dual);
        float w2j = unpack2(db.y).x;
        float sq  = fmaf(-2.f, dd.x, ci + w2j);
        float t   = 2.f - dd.y;
        float w   = __expf(-(sq * t) * t);
        ull  w2   = pack2(w, w);

        ulonglong2 ba = sBa[j];
        ull bz = sBz[j];
        ull xcb[8];
#pragma unroll
        for (int q = 0; q < 4; q++) {
            ull s = fma2(m[q], ba.x, fma2(m[4 + q], ba.y, fma2(m[8 + q], bz, b1ip[q])));
            float2 v = unpack2(s);
            v.x = fmaxf(v.x, 0.f);
            v.y = fmaxf(v.y, 0.f);
            xcb[2*q]     = pack2(v.x, v.x);
            xcb[2*q + 1] = pack2(v.y, v.y);
        }

        const ulonglong2* frow = (const ulonglong2*)&sF[j][hbase];
#pragma unroll
        for (int q2 = 0; q2 < 4; q2++) {
            ulonglong2 fq = frow[q2];
#pragma unroll
            for (int hh = 0; hh < 2; hh++) {
                int hp = 2 * q2 + hh;
                ull wf = mul2(w2, hh ? fq.y : fq.x);
                const ull* ar = a2p + hp * 8;
                ull s = b2p[hp];
#pragma unroll
                for (int c = 0; c < 8; c++) s = fma2(ar[c], xcb[c], s);
                float2 v = unpack2(s);          // relu via 2x FMNMX (ALU pipe)
                v.x = fmaxf(v.x, 0.f);
                v.y = fmaxf(v.y, 0.f);
                acc[hp] = fma2(pack2(v.x, v.y), wf, acc[hp]);
            }
        }
    }

    ulonglong2* outp = (ulonglong2*)&g_partial[blockIdx.y][i * HDIM + hbase];
#pragma unroll
    for (int q = 0; q < 4; q++) {
        ulonglong2 v; v.x = acc[2*q]; v.y = acc[2*q+1];
        outp[q] = v;
    }
}

// ---------------- reduce(9) + net_out + stats + FINAL GNORM (grid-spin) ----------------
__global__ void __launch_bounds__(512)
k_netout(const float* __restrict__ W1, const float* __restrict__ b1,
         const float* __restrict__ W2, const float* __restrict__ b2,
         const float* __restrict__ gamma, const float* __restrict__ beta,
         float* __restrict__ dout) {
    __shared__ float sW1t[HDIM * HDIM], sW2t[HDIM * HDIM], sb1[HDIM], sb2[HDIM];
    __shared__ float sX[16][HDIM];
    __shared__ float sG[16][4], sGq[16][4];
    __shared__ float sFin[512], sFinQ[512];
    __shared__ int   sLast;
    __shared__ unsigned sEpoch0;

    int tid  = threadIdx.x;
    int wid  = tid >> 5;
    int lane = tid & 31;
    int n    = blockIdx.x * 16 + wid;

    // snapshot the epoch BEFORE this block's stats arrival
    if (tid == 0) sEpoch0 = *(volatile unsigned*)&g_epoch;

    // issue the 9 partial-reduce loads FIRST (hide latency under weight staging)
    float xi = 0.f;
#pragma unroll
    for (int p = 0; p < JSPLIT; p++) xi += g_partial[p][n * HDIM + lane];

    for (int k = tid; k < HDIM * HDIM; k += 512) {
        int h = k >> 5, c = k & 31;
        sW1t[c * HDIM + h] = W1[k];
        sW2t[c * HDIM + h] = W2[k];
    }
    if (tid < HDIM) { sb1[tid] = b1[tid]; sb2[tid] = b2[tid]; }
    __syncthreads();

    sX[wid][lane] = xi;
    __syncwarp();

    float a0 = 0.f, a1 = 0.f, a2 = 0.f, a3 = 0.f;
#pragma unroll
    for (int c = 0; c < HDIM; c += 4) {
        a0 = fmaf(sW1t[(c    ) * HDIM + lane], sX[wid][c    ], a0);
        a1 = fmaf(sW1t[(c + 1) * HDIM + lane], sX[wid][c + 1], a1);
        a2 = fmaf(sW1t[(c + 2) * HDIM + lane], sX[wid][c + 2], a2);
        a3 = fmaf(sW1t[(c + 3) * HDIM + lane], sX[wid][c + 3], a3);
    }
    float z1 = leakyf(((a0 + a1) + (a2 + a3)) + sb1[lane]);

    __syncwarp();
    sX[wid][lane] = z1;
    __syncwarp();

    a0 = a1 = a2 = a3 = 0.f;
#pragma unroll
    for (int c = 0; c < HDIM; c += 4) {
        a0 = fmaf(sW2t[(c    ) * HDIM + lane], sX[wid][c    ], a0);
        a1 = fmaf(sW2t[(c + 1) * HDIM + lane], sX[wid][c + 1], a1);
        a2 = fmaf(sW2t[(c + 2) * HDIM + lane], sX[wid][c + 2], a2);
        a3 = fmaf(sW2t[(c + 3) * HDIM + lane], sX[wid][c + 3], a3);
    }
    float out = leakyf(((a0 + a1) + (a2 + a3)) + sb2[lane]);

    // block partials + last-block finalize into g_stats
    {
        float s = out, q = out * out;
#pragma unroll
        for (int off = 4; off; off >>= 1) {
            s += __shfl_down_sync(0xffffffffu, s, off, 8);
            q += __shfl_down_sync(0xffffffffu, q, off, 8);
        }
        if ((lane & 7) == 0) { sG[wid][lane >> 3] = s; sGq[wid][lane >> 3] = q; }
        __syncthreads();
        if (tid == 0) {
#pragma unroll
            for (int g = 0; g < 4; g++) {
                float S = 0.f, Q = 0.f;
                for (int w = 0; w < 16; w++) { S += sG[w][g]; Q += sGq[w][g]; }
                g_bs[blockIdx.x][g] = S; g_bq[blockIdx.x][g] = Q;
            }
            __threadfence();
            unsigned old = atomicAdd(&g_cnt, 1u);
            sLast = (old == NETBLKS - 1) ? 1 : 0;
        }
        __syncthreads();
        if (sLast) {
            int b = tid & 127, g = tid >> 7;
            sFin[g * 128 + b]  = g_bs[b][g];
            sFinQ[g * 128 + b] = g_bq[b][g];
            __syncthreads();
            for (int off = 64; off >= 1; off >>= 1) {
                if (b < off) {
                    sFin[g * 128 + b]  += sFin[g * 128 + b + off];
                    sFinQ[g * 128 + b] += sFinQ[g * 128 + b + off];
                }
                __syncthreads();
            }
            if (tid < 4) {
                double S = (double)sFin[tid * 128];
                double Q = (double)sFinQ[tid * 128];
                double cntd = (double)NPTS * 8.0;
                double mu = S / cntd;
                double var = Q / cntd - mu * mu;
                g_stats[tid]     = (float)mu;
                g_stats[4 + tid] = (float)(1.0 / sqrt(var + 1e-5));
            }
            if (tid == 0) g_cnt = 0;
        }
    }

    __syncthreads();
    if (sLast && tid == 0) {
        __threadfence();                       // publish g_stats before epoch bump
        atomicAdd((unsigned*)&g_epoch, 1u);
    }
    // grid-wide wait: all 128 blocks are co-resident (grid <= SM count)
    if (tid == 0) {
        while (*(volatile unsigned*)&g_epoch == sEpoch0) { }
    }
    __syncthreads();
    __threadfence();                           // acquire side

    // final group norm, values still in registers
    int g = lane >> 3;
    float mu = g_stats[g], rs = g_stats[4 + g];
    dout[n * HDIM + lane] = (out - mu) * rs * gamma[lane] + beta[lane];
}

// ---------------- launch ----------------
extern "C" void kernel_launch(void* const* d_in, const int* in_sizes, int n_in,
                              void* d_out, int out_size) {
    const float* points  = (const float*)d_in[0];
    const float* nuv     = (const float*)d_in[1];
    const float* feats   = (const float*)d_in[2];
    const float* W_in1   = (const float*)d_in[3];
    const float* b_in1   = (const float*)d_in[4];
    const float* W_in2   = (const float*)d_in[5];
    const float* b_in2   = (const float*)d_in[6];
    const float* g_in_w  = (const float*)d_in[7];
    const float* g_in_b  = (const float*)d_in[8];
    const float* A1      = (const float*)d_in[9];
    const float* A2      = (const float*)d_in[10];
    const float* W_out1  = (const float*)d_in[11];
    const float* b_out1  = (const float*)d_in[12];
    const float* W_out2  = (const float*)d_in[13];
    const float* b_out2  = (const float*)d_in[14];
    const float* g_out_w = (const float*)d_in[15];
    const float* g_out_b = (const float*)d_in[16];
    const float* B1      = (const float*)d_in[17];
    const float* B2      = (const float*)d_in[18];

    k_netin<<<NETBLKS, 512>>>(points, nuv, feats, W_in1, b_in1, W_in2, b_in2);
    k_pair<<<dim3(NPTS / 64, JSPLIT), TILE_I>>>(nuv, A1, B1, A2, B2, g_in_w, g_in_b);
    k_netout<<<NETBLKS, 512>>>(W_out1, b_out1, W_out2, b_out2,
                               g_out_w, g_out_b, (float*)d_out);
}